// round 10
// baseline (speedup 1.0000x reference)
#include <cuda_runtime.h>
#include <math.h>
#include <stdint.h>

#define B_ 8
#define N_ 4096
#define C_ 768
#define H_ 8
#define HD 96
#define M_ (B_*N_)        // 32768 rows
#define QKV_COLS (3*C_)   // 2304

// ---------------- scratch (device globals: allocation-free) ----------------
__device__ __align__(128) float g_G[(size_t)B_ * C_ * C_];        // x^T x per batch
__device__ __align__(128) float g_T[(size_t)B_ * C_ * 2 * C_];    // G @ [Wq|Wk]
__device__ __align__(128) float g_P[(size_t)B_ * C_ * C_];        // attn^T @ Wproj
__device__ __align__(128) float g_Q[(size_t)B_ * C_ * C_];        // Wv @ P_b
__device__ __align__(128) float g_S[B_ * H_ * HD * HD];           // logits/attn
__device__ __align__(128) float g_rn[B_ * 2 * C_];                // 1/max(||col||,eps)

// ---------------- packed fp32x2 helpers (FFMA2 path) ------------------------
typedef unsigned long long u64;
__device__ __forceinline__ u64 pack2(float lo, float hi) {
    u64 r; asm("mov.b64 %0, {%1,%2};" : "=l"(r) : "f"(lo), "f"(hi)); return r;
}
__device__ __forceinline__ void unpack2(u64 v, float& lo, float& hi) {
    asm("mov.b64 {%0,%1}, %2;" : "=f"(lo), "=f"(hi) : "l"(v));
}
__device__ __forceinline__ u64 ffma2(u64 a, u64 b, u64 c) {
    u64 d; asm("fma.rn.f32x2 %0, %1, %2, %3;" : "=l"(d) : "l"(a), "l"(b), "l"(c)); return d;
}

// ---------------- generic SGEMM 128x128 (T, Q, out) --------------------------
// Single-sync double-buffered mainloop: per tile  ldg(kt+1); compute(s);
// sts(s^1); sync.  Writers of buffer d are separated from its readers
// (previous tile's compute) by the end-of-tile barrier.
__global__ void __launch_bounds__(256, 2)
sgemm_kernel(const float* __restrict__ A, const float* __restrict__ Bm,
             float* __restrict__ C, const float* __restrict__ bias,
             int K, int lda, int ldb, int ldc,
             long long sAz, long long sCz, long long sBz, long long sBm)
{
    const int bz = blockIdx.z;
    const int m0 = blockIdx.y * 128, n0 = blockIdx.x * 128;
    A  += (size_t)bz * sAz;
    C  += (size_t)bz * sCz;
    Bm += (size_t)bz * sBz + (size_t)(m0 >> 12) * sBm;

    __shared__ float As[2][16][128];
    __shared__ float Bs[2][16][128];

    const int tid = threadIdx.x;
    const int tm = tid & 15, tn = tid >> 4;

    u64 acc[8][4];
#pragma unroll
    for (int i = 0; i < 8; i++)
#pragma unroll
        for (int j = 0; j < 4; j++) acc[i][j] = pack2(0.f, 0.f);

    float4 ra[2], rb[2];

    auto ldg = [&](int kt) {
#pragma unroll
        for (int l = 0; l < 2; l++) {
            int fid = tid + l * 256;
            int ar = fid >> 2, ac = fid & 3;
            ra[l] = *(const float4*)(A + (size_t)(m0 + ar) * lda + kt * 16 + ac * 4);
            int br = fid >> 5, bc = fid & 31;
            rb[l] = *(const float4*)(Bm + (size_t)(kt * 16 + br) * ldb + n0 + bc * 4);
        }
    };
    auto sts = [&](int s) {
#pragma unroll
        for (int l = 0; l < 2; l++) {
            int fid = tid + l * 256;
            int ar = fid >> 2, ac = fid & 3;
            As[s][ac * 4 + 0][ar] = ra[l].x; As[s][ac * 4 + 1][ar] = ra[l].y;
            As[s][ac * 4 + 2][ar] = ra[l].z; As[s][ac * 4 + 3][ar] = ra[l].w;
            int br = fid >> 5, bc = fid & 31;
            *(float4*)&Bs[s][br][bc * 4] = rb[l];
        }
    };

    ldg(0); sts(0);
    __syncthreads();

    const int KT = K >> 4;
    for (int kt = 0; kt < KT; ++kt) {
        const int s = kt & 1;
        if (kt + 1 < KT) ldg(kt + 1);
#pragma unroll
        for (int k = 0; k < 16; k++) {
            float4 a0 = *(const float4*)&As[s][k][tm * 8];
            float4 a1 = *(const float4*)&As[s][k][tm * 8 + 4];
            ulonglong2 b01 = *(const ulonglong2*)&Bs[s][k][tn * 8];
            ulonglong2 b23 = *(const ulonglong2*)&Bs[s][k][tn * 8 + 4];
            u64 b0 = b01.x, b1 = b01.y, b2 = b23.x, b3 = b23.y;
            float av[8] = {a0.x, a0.y, a0.z, a0.w, a1.x, a1.y, a1.z, a1.w};
#pragma unroll
            for (int i = 0; i < 8; i++) {
                u64 ad = pack2(av[i], av[i]);
                acc[i][0] = ffma2(ad, b0, acc[i][0]);
                acc[i][1] = ffma2(ad, b1, acc[i][1]);
                acc[i][2] = ffma2(ad, b2, acc[i][2]);
                acc[i][3] = ffma2(ad, b3, acc[i][3]);
            }
        }
        if (kt + 1 < KT) {
            sts(s ^ 1);
            __syncthreads();
        }
    }

#pragma unroll
    for (int i = 0; i < 8; i++) {
        int row = m0 + tm * 8 + i;
        float* cp = C + (size_t)row * ldc + n0 + tn * 8;
#pragma unroll
        for (int jp = 0; jp < 4; jp++) {
            float lo, hi; unpack2(acc[i][jp], lo, hi);
            if (bias) {
                lo += bias[n0 + tn * 8 + jp * 2];
                hi += bias[n0 + tn * 8 + jp * 2 + 1];
            }
            *(float2*)(cp + jp * 2) = make_float2(lo, hi);
        }
    }
}

// ---------------- zero G and S (single launch) -------------------------------
#define NG4 ((B_ * C_ * C_) / 4)                     // float4 count in g_G
#define NS4 ((B_ * H_ * HD * HD) / 4)                // float4 count in g_S
__global__ void zeroGS_kernel()
{
    size_t i = (size_t)blockIdx.x * 256 + threadIdx.x;
    if (i < NG4)
        *(float4*)(g_G + i * 4) = make_float4(0.f, 0.f, 0.f, 0.f);
    else
        *(float4*)(g_S + (i - NG4) * 4) = make_float4(0.f, 0.f, 0.f, 0.f);
}

// ---------------- Gram: G_b = x_b^T x_b, lower-tri tiles + mirror, k-split 4 -
#define GRAM_KSPLIT 4
#define GRAM_KLEN (N_ / GRAM_KSPLIT)

__global__ void __launch_bounds__(256, 2)
gram_kernel(const float* __restrict__ x)
{
    int i = 0, rem = blockIdx.x;
    while (rem > i) { rem -= i + 1; i++; }
    const int j = rem;
    const int b = blockIdx.y, kz = blockIdx.z;
    const float* xb = x + ((size_t)b * N_ + (size_t)kz * GRAM_KLEN) * C_;

    __shared__ float As[2][16][128];
    __shared__ float Bs[2][16][128];

    const int tid = threadIdx.x;
    const int tm = tid & 15, tn = tid >> 4;

    u64 acc[8][4];
#pragma unroll
    for (int q = 0; q < 8; q++)
#pragma unroll
        for (int p = 0; p < 4; p++) acc[q][p] = pack2(0.f, 0.f);

    float4 ra[2], rb[2];

    auto ldg = [&](int kt) {
#pragma unroll
        for (int l = 0; l < 2; l++) {
            int fid = tid + l * 256;
            int r = fid >> 5, cc = fid & 31;
            const float* src = xb + (size_t)(kt * 16 + r) * C_ + cc * 4;
            ra[l] = *(const float4*)(src + i * 128);
            rb[l] = *(const float4*)(src + j * 128);
        }
    };
    auto sts = [&](int s) {
#pragma unroll
        for (int l = 0; l < 2; l++) {
            int fid = tid + l * 256;
            int r = fid >> 5, cc = fid & 31;
            *(float4*)&As[s][r][cc * 4] = ra[l];
            *(float4*)&Bs[s][r][cc * 4] = rb[l];
        }
    };

    ldg(0); sts(0);
    __syncthreads();

    const int KT = GRAM_KLEN / 16;
    for (int kt = 0; kt < KT; ++kt) {
        const int s = kt & 1;
        if (kt + 1 < KT) ldg(kt + 1);
#pragma unroll
        for (int k = 0; k < 16; k++) {
            float4 a0 = *(const float4*)&As[s][k][tm * 8];
            float4 a1 = *(const float4*)&As[s][k][tm * 8 + 4];
            ulonglong2 b01 = *(const ulonglong2*)&Bs[s][k][tn * 8];
            ulonglong2 b23 = *(const ulonglong2*)&Bs[s][k][tn * 8 + 4];
            u64 b0 = b01.x, b1 = b01.y, b2 = b23.x, b3 = b23.y;
            float av[8] = {a0.x, a0.y, a0.z, a0.w, a1.x, a1.y, a1.z, a1.w};
#pragma unroll
            for (int q = 0; q < 8; q++) {
                u64 ad = pack2(av[q], av[q]);
                acc[q][0] = ffma2(ad, b0, acc[q][0]);
                acc[q][1] = ffma2(ad, b1, acc[q][1]);
                acc[q][2] = ffma2(ad, b2, acc[q][2]);
                acc[q][3] = ffma2(ad, b3, acc[q][3]);
            }
        }
        if (kt + 1 < KT) {
            sts(s ^ 1);
            __syncthreads();
        }
    }

    float* Gb = g_G + (size_t)b * C_ * C_;
#pragma unroll
    for (int q = 0; q < 8; q++) {
        int gi = i * 128 + tm * 8 + q;
#pragma unroll
        for (int p = 0; p < 4; p++) {
            float lo, hi; unpack2(acc[q][p], lo, hi);
            int gj = j * 128 + tn * 8 + 2 * p;
            atomicAdd(&Gb[(size_t)gi * C_ + gj], lo);
            atomicAdd(&Gb[(size_t)gi * C_ + gj + 1], hi);
            if (i != j) {
                atomicAdd(&Gb[(size_t)gj * C_ + gi], lo);
                atomicAdd(&Gb[(size_t)(gj + 1) * C_ + gi], hi);
            }
        }
    }
}

// ---------------- diag norms: rn[b,c] = 1/max(sqrt(<W[:,c],T_b[:,c]>),eps) ---
__global__ void diagnorm_kernel(const float* __restrict__ Wqkv)
{
    const int b = blockIdx.y;
    const int lane = threadIdx.x & 31;
    const int w = threadIdx.x >> 5;
    const int c = blockIdx.x * 32 + lane;
    const float* T = g_T + (size_t)b * C_ * (2 * C_);

    float s0 = 0.f, s1 = 0.f, s2 = 0.f, s3 = 0.f;
    for (int r0 = w * 4; r0 < C_; r0 += 32) {
        s0 += Wqkv[(size_t)(r0 + 0) * QKV_COLS + c] * T[(size_t)(r0 + 0) * (2 * C_) + c];
        s1 += Wqkv[(size_t)(r0 + 1) * QKV_COLS + c] * T[(size_t)(r0 + 1) * (2 * C_) + c];
        s2 += Wqkv[(size_t)(r0 + 2) * QKV_COLS + c] * T[(size_t)(r0 + 2) * (2 * C_) + c];
        s3 += Wqkv[(size_t)(r0 + 3) * QKV_COLS + c] * T[(size_t)(r0 + 3) * (2 * C_) + c];
    }
    __shared__ float red[8][32];
    red[w][lane] = (s0 + s1) + (s2 + s3);
    __syncthreads();
    if (w == 0) {
        float t = 0.f;
#pragma unroll
        for (int r = 0; r < 8; r++) t += red[r][lane];
        g_rn[b * (2 * C_) + c] = 1.f / fmaxf(sqrtf(t), 1e-12f);
    }
}

// ---------------- S_bh = Wq_h^T @ Tk_bh  (96x96, K=768, K-split 6) ----------
__global__ void __launch_bounds__(256)
s_kernel(const float* __restrict__ Wqkv)
{
    const int bh = blockIdx.x, b = bh >> 3, h = bh & 7;
    const int kc = blockIdx.y;                 // K chunk: t in [kc*4, kc*4+4)
    const int tid = threadIdx.x;
    const int te = tid & 15, td = tid >> 4;

    __shared__ float qs[32][96];
    __shared__ float ks[32][96];

    u64 acc2[6][3];
#pragma unroll
    for (int q = 0; q < 6; q++)
#pragma unroll
        for (int p = 0; p < 3; p++) acc2[q][p] = pack2(0.f, 0.f);

    const float* Wq = Wqkv + h * HD;
    const float* Tk = g_T + (size_t)b * C_ * (2 * C_) + C_ + h * HD;

    for (int t = kc * 4; t < kc * 4 + 4; t++) {
#pragma unroll
        for (int l = 0; l < 3; l++) {
            int fid = tid + l * 256;
            int r = fid / 24, cc = fid % 24;
            *(float4*)&qs[r][cc * 4] =
                *(const float4*)(Wq + (size_t)(t * 32 + r) * QKV_COLS + cc * 4);
            *(float4*)&ks[r][cc * 4] =
                *(const float4*)(Tk + (size_t)(t * 32 + r) * (2 * C_) + cc * 4);
        }
        __syncthreads();
#pragma unroll 4
        for (int r = 0; r < 32; r++) {
            const u64* bp = (const u64*)&ks[r][te * 6];
            u64 b0 = bp[0], b1 = bp[1], b2 = bp[2];
#pragma unroll
            for (int q = 0; q < 6; q++) {
                float a = qs[r][td * 6 + q];
                u64 ad = pack2(a, a);
                acc2[q][0] = ffma2(ad, b0, acc2[q][0]);
                acc2[q][1] = ffma2(ad, b1, acc2[q][1]);
                acc2[q][2] = ffma2(ad, b2, acc2[q][2]);
            }
        }
        __syncthreads();
    }
    float* Sp = g_S + (size_t)bh * HD * HD;
#pragma unroll
    for (int q = 0; q < 6; q++)
#pragma unroll
        for (int p = 0; p < 3; p++) {
            float lo, hi; unpack2(acc2[q][p], lo, hi);
            atomicAdd(&Sp[(td * 6 + q) * HD + te * 6 + 2 * p], lo);
            atomicAdd(&Sp[(td * 6 + q) * HD + te * 6 + 2 * p + 1], hi);
        }
}

// ---------------- scale + softmax (in place in g_S) --------------------------
__global__ void softmax_kernel(const float* __restrict__ temp)
{
    const int bh = blockIdx.x, b = bh >> 3, h = bh & 7;
    const int d = threadIdx.x;
    if (d >= HD) return;
    float* row = g_S + (size_t)bh * HD * HD + d * HD;
    const float rq = g_rn[b * (2 * C_) + h * HD + d] * temp[h];
    const float* rk = g_rn + b * (2 * C_) + C_ + h * HD;

    float vals[HD];
    float m = -1e30f;
    for (int e = 0; e < HD; e++) {
        float v = row[e] * rq * rk[e];
        vals[e] = v;
        if (v > m) m = v;
    }
    float ssum = 0.f;
    for (int e = 0; e < HD; e++) {
        float v = expf(vals[e] - m);
        vals[e] = v;
        ssum += v;
    }
    float inv = 1.f / ssum;
    for (int e = 0; e < HD; e++) row[e] = vals[e] * inv;
}

// ---------------- P_b[h*96+e, j] = sum_d attn_bh[d,e] * Wproj[h*96+d, j] -----
__global__ void __launch_bounds__(256)
p_kernel(const float* __restrict__ Wproj)
{
    const int bh = blockIdx.x, b = bh >> 3, h = bh & 7;
    const int jt = blockIdx.y;
    const int tid = threadIdx.x;
    const int er = tid >> 5, lane = tid & 31;

    __shared__ float ats[32][96];
    __shared__ float ws[32][128];

    u64 acc2[12][2];
#pragma unroll
    for (int q = 0; q < 12; q++) { acc2[q][0] = pack2(0.f, 0.f); acc2[q][1] = pack2(0.f, 0.f); }

    const float* Sp = g_S + (size_t)bh * HD * HD;
    const float* Wp = Wproj + (size_t)(h * HD) * C_ + jt * 128;

    for (int dc = 0; dc < 3; dc++) {
        __syncthreads();
#pragma unroll
        for (int l = 0; l < 3; l++) {
            int fid = tid + l * 256;
            int r = fid / 24, cc = fid % 24;
            *(float4*)&ats[r][cc * 4] = *(const float4*)(Sp + (size_t)(dc * 32 + r) * HD + cc * 4);
        }
#pragma unroll
        for (int l = 0; l < 4; l++) {
            int fid = tid + l * 256;
            int r = fid >> 5, cc = fid & 31;
            *(float4*)&ws[r][cc * 4] = *(const float4*)(Wp + (size_t)(dc * 32 + r) * C_ + cc * 4);
        }
        __syncthreads();
#pragma unroll 4
        for (int d = 0; d < 32; d++) {
            u64 w01 = *(const u64*)&ws[d][lane * 4];
            u64 w23 = *(const u64*)&ws[d][lane * 4 + 2];
#pragma unroll
            for (int q = 0; q < 12; q++) {
                float a = ats[d][er * 12 + q];
                u64 ad = pack2(a, a);
                acc2[q][0] = ffma2(ad, w01, acc2[q][0]);
                acc2[q][1] = ffma2(ad, w23, acc2[q][1]);
            }
        }
    }

    float* Pb = g_P + (size_t)b * C_ * C_;
#pragma unroll
    for (int q = 0; q < 12; q++) {
        float f0, f1, f2, f3;
        unpack2(acc2[q][0], f0, f1);
        unpack2(acc2[q][1], f2, f3);
        *(float4*)&Pb[(size_t)(h * HD + er * 12 + q) * C_ + jt * 128 + lane * 4] =
            make_float4(f0, f1, f2, f3);
    }
}

// ---------------- launch ----------------------------------------------------
extern "C" void kernel_launch(void* const* d_in, const int* in_sizes, int n_in,
                              void* d_out, int out_size)
{
    const float* x     = (const float*)d_in[0];
    const float* Wqkv  = (const float*)d_in[1];
    const float* temp  = (const float*)d_in[2];
    const float* Wproj = (const float*)d_in[3];
    const float* bproj = (const float*)d_in[4];
    float* out = (float*)d_out;

    static float *dG = nullptr, *dT = nullptr, *dP = nullptr, *dQ = nullptr;
    if (!dG) {
        cudaGetSymbolAddress((void**)&dG, g_G);
        cudaGetSymbolAddress((void**)&dT, g_T);
        cudaGetSymbolAddress((void**)&dP, g_P);
        cudaGetSymbolAddress((void**)&dQ, g_Q);
    }

    // 1) zero G and S, then G_b = x_b^T x_b (lower tiles + mirror, k-split 4)
    zeroGS_kernel<<<(NG4 + NS4) / 256, 256>>>();
    gram_kernel<<<dim3(21, B_, GRAM_KSPLIT), 256>>>(x);

    // 2) T_b = G_b @ [Wq|Wk]
    sgemm_kernel<<<dim3((2 * C_) / 128, C_ / 128, B_), 256>>>(
        dG, Wqkv, dT, nullptr, C_, C_, QKV_COLS, 2 * C_,
        (long long)C_ * C_, (long long)C_ * 2 * C_, 0, 0);

    // 3) reciprocal norms from diag(W^T T)
    diagnorm_kernel<<<dim3((2 * C_) / 32, B_), 256>>>(Wqkv);

    // 4) S_bh = Wq_h^T Tk_bh (K-split 6), then softmax
    s_kernel<<<dim3(B_ * H_, 6), 256>>>(Wqkv);
    softmax_kernel<<<B_ * H_, 96>>>(temp);

    // 5) P_b = attn^T-blocks @ Wproj
    p_kernel<<<dim3(B_ * H_, C_ / 128), 256>>>(Wproj);

    // 6) Q_b = Wv @ P_b  (batched over B; Wv = cols [2C,3C) of Wqkv)
    sgemm_kernel<<<dim3(C_ / 128, C_ / 128, B_), 256>>>(
        Wqkv + 2 * C_, dP, dQ, nullptr, C_, QKV_COLS, C_, C_,
        0, (long long)C_ * C_, (long long)C_ * C_, 0);

    // 7) out = x @ Q_b + bproj  (Q selected per 4096-row batch block)
    sgemm_kernel<<<dim3(C_ / 128, M_ / 128, 1), 256>>>(
        x, dQ, out, bproj, C_, C_, C_, C_, 0, 0, 0, (long long)C_ * C_);
}

// round 11
// speedup vs baseline: 1.0639x; 1.0639x over previous
#include <cuda_runtime.h>
#include <math.h>
#include <stdint.h>

#define B_ 8
#define N_ 4096
#define C_ 768
#define H_ 8
#define HD 96
#define M_ (B_*N_)        // 32768 rows
#define QKV_COLS (3*C_)   // 2304

// ---------------- scratch (device globals: allocation-free) ----------------
__device__ __align__(128) float g_G[(size_t)B_ * C_ * C_];        // x^T x per batch
__device__ __align__(128) float g_T[(size_t)B_ * C_ * 2 * C_];    // G @ [Wq|Wk]
__device__ __align__(128) float g_P[(size_t)B_ * C_ * C_];        // attn^T @ Wproj
__device__ __align__(128) float g_Q[(size_t)B_ * C_ * C_];        // Wv @ P_b
__device__ __align__(128) float g_S[B_ * H_ * HD * HD];           // logits/attn
__device__ __align__(128) float g_rn[B_ * 2 * C_];                // 1/max(||col||,eps)

// ---------------- packed fp32x2 helpers (FFMA2 path) ------------------------
typedef unsigned long long u64;
__device__ __forceinline__ u64 pack2(float lo, float hi) {
    u64 r; asm("mov.b64 %0, {%1,%2};" : "=l"(r) : "f"(lo), "f"(hi)); return r;
}
__device__ __forceinline__ void unpack2(u64 v, float& lo, float& hi) {
    asm("mov.b64 {%0,%1}, %2;" : "=f"(lo), "=f"(hi) : "l"(v));
}
__device__ __forceinline__ u64 ffma2(u64 a, u64 b, u64 c) {
    u64 d; asm("fma.rn.f32x2 %0, %1, %2, %3;" : "=l"(d) : "l"(a), "l"(b), "l"(c)); return d;
}

// ---------------- generic SGEMM 128x128 (T, Q, out) --------------------------
// Two-sync double-buffered mainloop (proven fastest: round-9 config).
__global__ void __launch_bounds__(256, 2)
sgemm_kernel(const float* __restrict__ A, const float* __restrict__ Bm,
             float* __restrict__ C, const float* __restrict__ bias,
             int K, int lda, int ldb, int ldc,
             long long sAz, long long sCz, long long sBz, long long sBm)
{
    const int bz = blockIdx.z;
    const int m0 = blockIdx.y * 128, n0 = blockIdx.x * 128;
    A  += (size_t)bz * sAz;
    C  += (size_t)bz * sCz;
    Bm += (size_t)bz * sBz + (size_t)(m0 >> 12) * sBm;

    __shared__ float As[2][16][128];
    __shared__ float Bs[2][16][128];

    const int tid = threadIdx.x;
    const int tm = tid & 15, tn = tid >> 4;

    u64 acc[8][4];
#pragma unroll
    for (int i = 0; i < 8; i++)
#pragma unroll
        for (int j = 0; j < 4; j++) acc[i][j] = pack2(0.f, 0.f);

    float4 ra[2], rb[2];
#pragma unroll
    for (int l = 0; l < 2; l++) {
        int fid = tid + l * 256;
        int ar = fid >> 2, ac = fid & 3;
        ra[l] = *(const float4*)(A + (size_t)(m0 + ar) * lda + ac * 4);
        int br = fid >> 5, bc = fid & 31;
        rb[l] = *(const float4*)(Bm + (size_t)br * ldb + n0 + bc * 4);
    }
#pragma unroll
    for (int l = 0; l < 2; l++) {
        int fid = tid + l * 256;
        int ar = fid >> 2, ac = fid & 3;
        As[0][ac * 4 + 0][ar] = ra[l].x; As[0][ac * 4 + 1][ar] = ra[l].y;
        As[0][ac * 4 + 2][ar] = ra[l].z; As[0][ac * 4 + 3][ar] = ra[l].w;
        int br = fid >> 5, bc = fid & 31;
        *(float4*)&Bs[0][br][bc * 4] = rb[l];
    }
    __syncthreads();

    const int KT = K >> 4;
    for (int kt = 0; kt < KT; ++kt) {
        const int s = kt & 1;
        if (kt + 1 < KT) {
            int k0 = (kt + 1) << 4;
#pragma unroll
            for (int l = 0; l < 2; l++) {
                int fid = tid + l * 256;
                int ar = fid >> 2, ac = fid & 3;
                ra[l] = *(const float4*)(A + (size_t)(m0 + ar) * lda + k0 + ac * 4);
                int br = fid >> 5, bc = fid & 31;
                rb[l] = *(const float4*)(Bm + (size_t)(k0 + br) * ldb + n0 + bc * 4);
            }
        }
#pragma unroll
        for (int k = 0; k < 16; k++) {
            float4 a0 = *(const float4*)&As[s][k][tm * 8];
            float4 a1 = *(const float4*)&As[s][k][tm * 8 + 4];
            u64 b0 = *(const u64*)&Bs[s][k][tn * 8 + 0];
            u64 b1 = *(const u64*)&Bs[s][k][tn * 8 + 2];
            u64 b2 = *(const u64*)&Bs[s][k][tn * 8 + 4];
            u64 b3 = *(const u64*)&Bs[s][k][tn * 8 + 6];
            float av[8] = {a0.x, a0.y, a0.z, a0.w, a1.x, a1.y, a1.z, a1.w};
#pragma unroll
            for (int i = 0; i < 8; i++) {
                u64 ad = pack2(av[i], av[i]);
                acc[i][0] = ffma2(ad, b0, acc[i][0]);
                acc[i][1] = ffma2(ad, b1, acc[i][1]);
                acc[i][2] = ffma2(ad, b2, acc[i][2]);
                acc[i][3] = ffma2(ad, b3, acc[i][3]);
            }
        }
        __syncthreads();
        if (kt + 1 < KT) {
            const int d = s ^ 1;
#pragma unroll
            for (int l = 0; l < 2; l++) {
                int fid = tid + l * 256;
                int ar = fid >> 2, ac = fid & 3;
                As[d][ac * 4 + 0][ar] = ra[l].x; As[d][ac * 4 + 1][ar] = ra[l].y;
                As[d][ac * 4 + 2][ar] = ra[l].z; As[d][ac * 4 + 3][ar] = ra[l].w;
                int br = fid >> 5, bc = fid & 31;
                *(float4*)&Bs[d][br][bc * 4] = rb[l];
            }
            __syncthreads();
        }
    }

#pragma unroll
    for (int i = 0; i < 8; i++) {
        int row = m0 + tm * 8 + i;
        float* cp = C + (size_t)row * ldc + n0 + tn * 8;
#pragma unroll
        for (int jp = 0; jp < 4; jp++) {
            float lo, hi; unpack2(acc[i][jp], lo, hi);
            if (bias) {
                lo += bias[n0 + tn * 8 + jp * 2];
                hi += bias[n0 + tn * 8 + jp * 2 + 1];
            }
            *(float2*)(cp + jp * 2) = make_float2(lo, hi);
        }
    }
}

// ---------------- zero G and S (single launch) -------------------------------
#define NG4 ((B_ * C_ * C_) / 4)                     // float4 count in g_G
#define NS4 ((B_ * H_ * HD * HD) / 4)                // float4 count in g_S
__global__ void zeroGS_kernel()
{
    size_t i = (size_t)blockIdx.x * 256 + threadIdx.x;
    if (i < NG4)
        *(float4*)(g_G + i * 4) = make_float4(0.f, 0.f, 0.f, 0.f);
    else
        *(float4*)(g_S + (i - NG4) * 4) = make_float4(0.f, 0.f, 0.f, 0.f);
}

// ---------------- Gram: G_b = x_b^T x_b, lower-tri tiles + mirror, k-split 4 -
#define GRAM_KSPLIT 4
#define GRAM_KLEN (N_ / GRAM_KSPLIT)

__global__ void __launch_bounds__(256, 2)
gram_kernel(const float* __restrict__ x)
{
    int i = 0, rem = blockIdx.x;
    while (rem > i) { rem -= i + 1; i++; }
    const int j = rem;
    const int b = blockIdx.y, kz = blockIdx.z;
    const float* xb = x + ((size_t)b * N_ + (size_t)kz * GRAM_KLEN) * C_;

    __shared__ float As[2][16][128];
    __shared__ float Bs[2][16][128];

    const int tid = threadIdx.x;
    const int tm = tid & 15, tn = tid >> 4;

    u64 acc[8][4];
#pragma unroll
    for (int q = 0; q < 8; q++)
#pragma unroll
        for (int p = 0; p < 4; p++) acc[q][p] = pack2(0.f, 0.f);

    float4 ra[2], rb[2];

    auto ldg = [&](int kt) {
#pragma unroll
        for (int l = 0; l < 2; l++) {
            int fid = tid + l * 256;
            int r = fid >> 5, cc = fid & 31;
            const float* src = xb + (size_t)(kt * 16 + r) * C_ + cc * 4;
            ra[l] = *(const float4*)(src + i * 128);
            rb[l] = *(const float4*)(src + j * 128);
        }
    };
    auto sts = [&](int s) {
#pragma unroll
        for (int l = 0; l < 2; l++) {
            int fid = tid + l * 256;
            int r = fid >> 5, cc = fid & 31;
            *(float4*)&As[s][r][cc * 4] = ra[l];
            *(float4*)&Bs[s][r][cc * 4] = rb[l];
        }
    };

    ldg(0); sts(0);
    __syncthreads();

    const int KT = GRAM_KLEN / 16;
    for (int kt = 0; kt < KT; ++kt) {
        const int s = kt & 1;
        if (kt + 1 < KT) ldg(kt + 1);
#pragma unroll
        for (int k = 0; k < 16; k++) {
            float4 a0 = *(const float4*)&As[s][k][tm * 8];
            float4 a1 = *(const float4*)&As[s][k][tm * 8 + 4];
            u64 b0 = *(const u64*)&Bs[s][k][tn * 8 + 0];
            u64 b1 = *(const u64*)&Bs[s][k][tn * 8 + 2];
            u64 b2 = *(const u64*)&Bs[s][k][tn * 8 + 4];
            u64 b3 = *(const u64*)&Bs[s][k][tn * 8 + 6];
            float av[8] = {a0.x, a0.y, a0.z, a0.w, a1.x, a1.y, a1.z, a1.w};
#pragma unroll
            for (int q = 0; q < 8; q++) {
                u64 ad = pack2(av[q], av[q]);
                acc[q][0] = ffma2(ad, b0, acc[q][0]);
                acc[q][1] = ffma2(ad, b1, acc[q][1]);
                acc[q][2] = ffma2(ad, b2, acc[q][2]);
                acc[q][3] = ffma2(ad, b3, acc[q][3]);
            }
        }
        __syncthreads();
        if (kt + 1 < KT) {
            sts(s ^ 1);
            __syncthreads();
        }
    }

    float* Gb = g_G + (size_t)b * C_ * C_;
#pragma unroll
    for (int q = 0; q < 8; q++) {
        int gi = i * 128 + tm * 8 + q;
#pragma unroll
        for (int p = 0; p < 4; p++) {
            float lo, hi; unpack2(acc[q][p], lo, hi);
            int gj = j * 128 + tn * 8 + 2 * p;
            atomicAdd(&Gb[(size_t)gi * C_ + gj], lo);
            atomicAdd(&Gb[(size_t)gi * C_ + gj + 1], hi);
            if (i != j) {
                atomicAdd(&Gb[(size_t)gj * C_ + gi], lo);
                atomicAdd(&Gb[(size_t)(gj + 1) * C_ + gi], hi);
            }
        }
    }
}

// ---------------- diag norms: rn[b,c] = 1/max(sqrt(<W[:,c],T_b[:,c]>),eps) ---
__global__ void diagnorm_kernel(const float* __restrict__ Wqkv)
{
    const int b = blockIdx.y;
    const int lane = threadIdx.x & 31;
    const int w = threadIdx.x >> 5;
    const int c = blockIdx.x * 32 + lane;
    const float* T = g_T + (size_t)b * C_ * (2 * C_);

    float s0 = 0.f, s1 = 0.f, s2 = 0.f, s3 = 0.f;
    for (int r0 = w * 4; r0 < C_; r0 += 32) {
        s0 += Wqkv[(size_t)(r0 + 0) * QKV_COLS + c] * T[(size_t)(r0 + 0) * (2 * C_) + c];
        s1 += Wqkv[(size_t)(r0 + 1) * QKV_COLS + c] * T[(size_t)(r0 + 1) * (2 * C_) + c];
        s2 += Wqkv[(size_t)(r0 + 2) * QKV_COLS + c] * T[(size_t)(r0 + 2) * (2 * C_) + c];
        s3 += Wqkv[(size_t)(r0 + 3) * QKV_COLS + c] * T[(size_t)(r0 + 3) * (2 * C_) + c];
    }
    __shared__ float red[8][32];
    red[w][lane] = (s0 + s1) + (s2 + s3);
    __syncthreads();
    if (w == 0) {
        float t = 0.f;
#pragma unroll
        for (int r = 0; r < 8; r++) t += red[r][lane];
        g_rn[b * (2 * C_) + c] = 1.f / fmaxf(sqrtf(t), 1e-12f);
    }
}

// ---------------- S_bh = Wq_h^T @ Tk_bh  (96x96, K=768, K-split 6) ----------
__global__ void __launch_bounds__(256)
s_kernel(const float* __restrict__ Wqkv)
{
    const int bh = blockIdx.x, b = bh >> 3, h = bh & 7;
    const int kc = blockIdx.y;                 // K chunk: t in [kc*4, kc*4+4)
    const int tid = threadIdx.x;
    const int te = tid & 15, td = tid >> 4;

    __shared__ float qs[32][96];
    __shared__ float ks[32][96];

    u64 acc2[6][3];
#pragma unroll
    for (int q = 0; q < 6; q++)
#pragma unroll
        for (int p = 0; p < 3; p++) acc2[q][p] = pack2(0.f, 0.f);

    const float* Wq = Wqkv + h * HD;
    const float* Tk = g_T + (size_t)b * C_ * (2 * C_) + C_ + h * HD;

    for (int t = kc * 4; t < kc * 4 + 4; t++) {
#pragma unroll
        for (int l = 0; l < 3; l++) {
            int fid = tid + l * 256;
            int r = fid / 24, cc = fid % 24;
            *(float4*)&qs[r][cc * 4] =
                *(const float4*)(Wq + (size_t)(t * 32 + r) * QKV_COLS + cc * 4);
            *(float4*)&ks[r][cc * 4] =
                *(const float4*)(Tk + (size_t)(t * 32 + r) * (2 * C_) + cc * 4);
        }
        __syncthreads();
#pragma unroll 4
        for (int r = 0; r < 32; r++) {
            const u64* bp = (const u64*)&ks[r][te * 6];
            u64 b0 = bp[0], b1 = bp[1], b2 = bp[2];
#pragma unroll
            for (int q = 0; q < 6; q++) {
                float a = qs[r][td * 6 + q];
                u64 ad = pack2(a, a);
                acc2[q][0] = ffma2(ad, b0, acc2[q][0]);
                acc2[q][1] = ffma2(ad, b1, acc2[q][1]);
                acc2[q][2] = ffma2(ad, b2, acc2[q][2]);
            }
        }
        __syncthreads();
    }
    float* Sp = g_S + (size_t)bh * HD * HD;
#pragma unroll
    for (int q = 0; q < 6; q++)
#pragma unroll
        for (int p = 0; p < 3; p++) {
            float lo, hi; unpack2(acc2[q][p], lo, hi);
            atomicAdd(&Sp[(td * 6 + q) * HD + te * 6 + 2 * p], lo);
            atomicAdd(&Sp[(td * 6 + q) * HD + te * 6 + 2 * p + 1], hi);
        }
}

// ---------------- scale + softmax (in place in g_S) --------------------------
__global__ void softmax_kernel(const float* __restrict__ temp)
{
    const int bh = blockIdx.x, b = bh >> 3, h = bh & 7;
    const int d = threadIdx.x;
    if (d >= HD) return;
    float* row = g_S + (size_t)bh * HD * HD + d * HD;
    const float rq = g_rn[b * (2 * C_) + h * HD + d] * temp[h];
    const float* rk = g_rn + b * (2 * C_) + C_ + h * HD;

    float vals[HD];
    float m = -1e30f;
    for (int e = 0; e < HD; e++) {
        float v = row[e] * rq * rk[e];
        vals[e] = v;
        if (v > m) m = v;
    }
    float ssum = 0.f;
    for (int e = 0; e < HD; e++) {
        float v = expf(vals[e] - m);
        vals[e] = v;
        ssum += v;
    }
    float inv = 1.f / ssum;
    for (int e = 0; e < HD; e++) row[e] = vals[e] * inv;
}

// ---------------- P_b[h*96+e, j] = sum_d attn_bh[d,e] * Wproj[h*96+d, j] -----
__global__ void __launch_bounds__(256)
p_kernel(const float* __restrict__ Wproj)
{
    const int bh = blockIdx.x, b = bh >> 3, h = bh & 7;
    const int jt = blockIdx.y;
    const int tid = threadIdx.x;
    const int er = tid >> 5, lane = tid & 31;

    __shared__ float ats[32][96];
    __shared__ float ws[32][128];

    u64 acc2[12][2];
#pragma unroll
    for (int q = 0; q < 12; q++) { acc2[q][0] = pack2(0.f, 0.f); acc2[q][1] = pack2(0.f, 0.f); }

    const float* Sp = g_S + (size_t)bh * HD * HD;
    const float* Wp = Wproj + (size_t)(h * HD) * C_ + jt * 128;

    for (int dc = 0; dc < 3; dc++) {
        __syncthreads();
#pragma unroll
        for (int l = 0; l < 3; l++) {
            int fid = tid + l * 256;
            int r = fid / 24, cc = fid % 24;
            *(float4*)&ats[r][cc * 4] = *(const float4*)(Sp + (size_t)(dc * 32 + r) * HD + cc * 4);
        }
#pragma unroll
        for (int l = 0; l < 4; l++) {
            int fid = tid + l * 256;
            int r = fid >> 5, cc = fid & 31;
            *(float4*)&ws[r][cc * 4] = *(const float4*)(Wp + (size_t)(dc * 32 + r) * C_ + cc * 4);
        }
        __syncthreads();
#pragma unroll 4
        for (int d = 0; d < 32; d++) {
            u64 w01 = *(const u64*)&ws[d][lane * 4];
            u64 w23 = *(const u64*)&ws[d][lane * 4 + 2];
#pragma unroll
            for (int q = 0; q < 12; q++) {
                float a = ats[d][er * 12 + q];
                u64 ad = pack2(a, a);
                acc2[q][0] = ffma2(ad, w01, acc2[q][0]);
                acc2[q][1] = ffma2(ad, w23, acc2[q][1]);
            }
        }
    }

    float* Pb = g_P + (size_t)b * C_ * C_;
#pragma unroll
    for (int q = 0; q < 12; q++) {
        float f0, f1, f2, f3;
        unpack2(acc2[q][0], f0, f1);
        unpack2(acc2[q][1], f2, f3);
        *(float4*)&Pb[(size_t)(h * HD + er * 12 + q) * C_ + jt * 128 + lane * 4] =
            make_float4(f0, f1, f2, f3);
    }
}

// ---------------- launch ----------------------------------------------------
extern "C" void kernel_launch(void* const* d_in, const int* in_sizes, int n_in,
                              void* d_out, int out_size)
{
    const float* x     = (const float*)d_in[0];
    const float* Wqkv  = (const float*)d_in[1];
    const float* temp  = (const float*)d_in[2];
    const float* Wproj = (const float*)d_in[3];
    const float* bproj = (const float*)d_in[4];
    float* out = (float*)d_out;

    static float *dG = nullptr, *dT = nullptr, *dP = nullptr, *dQ = nullptr;
    if (!dG) {
        cudaGetSymbolAddress((void**)&dG, g_G);
        cudaGetSymbolAddress((void**)&dT, g_T);
        cudaGetSymbolAddress((void**)&dP, g_P);
        cudaGetSymbolAddress((void**)&dQ, g_Q);
    }

    // 1) zero G and S, then G_b = x_b^T x_b (lower tiles + mirror, k-split 4)
    zeroGS_kernel<<<(NG4 + NS4) / 256, 256>>>();
    gram_kernel<<<dim3(21, B_, GRAM_KSPLIT), 256>>>(x);

    // 2) T_b = G_b @ [Wq|Wk]
    sgemm_kernel<<<dim3((2 * C_) / 128, C_ / 128, B_), 256>>>(
        dG, Wqkv, dT, nullptr, C_, C_, QKV_COLS, 2 * C_,
        (long long)C_ * C_, (long long)C_ * 2 * C_, 0, 0);

    // 3) S partial sums first (atomic-heavy; starts while diagnorm queues)
    s_kernel<<<dim3(B_ * H_, 6), 256>>>(Wqkv);

    // 4) reciprocal norms from diag(W^T T)
    diagnorm_kernel<<<dim3((2 * C_) / 32, B_), 256>>>(Wqkv);

    // 5) scale + softmax
    softmax_kernel<<<B_ * H_, 96>>>(temp);

    // 6) P_b = attn^T-blocks @ Wproj
    p_kernel<<<dim3(B_ * H_, C_ / 128), 256>>>(Wproj);

    // 7) Q_b = Wv @ P_b  (batched over B; Wv = cols [2C,3C) of Wqkv)
    sgemm_kernel<<<dim3(C_ / 128, C_ / 128, B_), 256>>>(
        Wqkv + 2 * C_, dP, dQ, nullptr, C_, QKV_COLS, C_, C_,
        0, (long long)C_ * C_, (long long)C_ * C_, 0);

    // 8) out = x @ Q_b + bproj  (Q selected per 4096-row batch block)
    sgemm_kernel<<<dim3(C_ / 128, M_ / 128, 1), 256>>>(
        x, dQ, out, bproj, C_, C_, C_, C_, 0, 0, 0, (long long)C_ * C_);
}

// round 12
// speedup vs baseline: 1.0645x; 1.0006x over previous
#include <cuda_runtime.h>
#include <math.h>
#include <stdint.h>

#define B_ 8
#define N_ 4096
#define C_ 768
#define H_ 8
#define HD 96
#define M_ (B_*N_)        // 32768 rows
#define QKV_COLS (3*C_)   // 2304
#define SKC 6             // s_kernel K-split

// ---------------- scratch (device globals: allocation-free) ----------------
__device__ __align__(128) float g_G[(size_t)B_ * C_ * C_];        // x^T x per batch
__device__ __align__(128) float g_T[(size_t)B_ * C_ * 2 * C_];    // G @ [Wq|Wk]
__device__ __align__(128) float g_P[(size_t)B_ * C_ * C_];        // attn^T @ Wproj
__device__ __align__(128) float g_Q[(size_t)B_ * C_ * C_];        // Wv @ P_b
__device__ __align__(128) float g_S[B_ * H_ * HD * HD];           // attn (post-softmax)
__device__ __align__(128) float g_S6[SKC * B_ * H_ * HD * HD];    // logit partials
__device__ __align__(128) float g_rn[B_ * 2 * C_];                // 1/max(||col||,eps)

// ---------------- packed fp32x2 helpers (FFMA2 path) ------------------------
typedef unsigned long long u64;
__device__ __forceinline__ u64 pack2(float lo, float hi) {
    u64 r; asm("mov.b64 %0, {%1,%2};" : "=l"(r) : "f"(lo), "f"(hi)); return r;
}
__device__ __forceinline__ void unpack2(u64 v, float& lo, float& hi) {
    asm("mov.b64 {%0,%1}, %2;" : "=f"(lo), "=f"(hi) : "l"(v));
}
__device__ __forceinline__ u64 ffma2(u64 a, u64 b, u64 c) {
    u64 d; asm("fma.rn.f32x2 %0, %1, %2, %3;" : "=l"(d) : "l"(a), "l"(b), "l"(c)); return d;
}

// ---------------- generic SGEMM 128x128 (T, Q, out) --------------------------
// Two-sync double-buffered mainloop (proven fastest config).
__global__ void __launch_bounds__(256, 2)
sgemm_kernel(const float* __restrict__ A, const float* __restrict__ Bm,
             float* __restrict__ C, const float* __restrict__ bias,
             int K, int lda, int ldb, int ldc,
             long long sAz, long long sCz, long long sBz, long long sBm)
{
    const int bz = blockIdx.z;
    const int m0 = blockIdx.y * 128, n0 = blockIdx.x * 128;
    A  += (size_t)bz * sAz;
    C  += (size_t)bz * sCz;
    Bm += (size_t)bz * sBz + (size_t)(m0 >> 12) * sBm;

    __shared__ float As[2][16][128];
    __shared__ float Bs[2][16][128];

    const int tid = threadIdx.x;
    const int tm = tid & 15, tn = tid >> 4;

    u64 acc[8][4];
#pragma unroll
    for (int i = 0; i < 8; i++)
#pragma unroll
        for (int j = 0; j < 4; j++) acc[i][j] = pack2(0.f, 0.f);

    float4 ra[2], rb[2];
#pragma unroll
    for (int l = 0; l < 2; l++) {
        int fid = tid + l * 256;
        int ar = fid >> 2, ac = fid & 3;
        ra[l] = *(const float4*)(A + (size_t)(m0 + ar) * lda + ac * 4);
        int br = fid >> 5, bc = fid & 31;
        rb[l] = *(const float4*)(Bm + (size_t)br * ldb + n0 + bc * 4);
    }
#pragma unroll
    for (int l = 0; l < 2; l++) {
        int fid = tid + l * 256;
        int ar = fid >> 2, ac = fid & 3;
        As[0][ac * 4 + 0][ar] = ra[l].x; As[0][ac * 4 + 1][ar] = ra[l].y;
        As[0][ac * 4 + 2][ar] = ra[l].z; As[0][ac * 4 + 3][ar] = ra[l].w;
        int br = fid >> 5, bc = fid & 31;
        *(float4*)&Bs[0][br][bc * 4] = rb[l];
    }
    __syncthreads();

    const int KT = K >> 4;
    for (int kt = 0; kt < KT; ++kt) {
        const int s = kt & 1;
        if (kt + 1 < KT) {
            int k0 = (kt + 1) << 4;
#pragma unroll
            for (int l = 0; l < 2; l++) {
                int fid = tid + l * 256;
                int ar = fid >> 2, ac = fid & 3;
                ra[l] = *(const float4*)(A + (size_t)(m0 + ar) * lda + k0 + ac * 4);
                int br = fid >> 5, bc = fid & 31;
                rb[l] = *(const float4*)(Bm + (size_t)(k0 + br) * ldb + n0 + bc * 4);
            }
        }
#pragma unroll
        for (int k = 0; k < 16; k++) {
            float4 a0 = *(const float4*)&As[s][k][tm * 8];
            float4 a1 = *(const float4*)&As[s][k][tm * 8 + 4];
            u64 b0 = *(const u64*)&Bs[s][k][tn * 8 + 0];
            u64 b1 = *(const u64*)&Bs[s][k][tn * 8 + 2];
            u64 b2 = *(const u64*)&Bs[s][k][tn * 8 + 4];
            u64 b3 = *(const u64*)&Bs[s][k][tn * 8 + 6];
            float av[8] = {a0.x, a0.y, a0.z, a0.w, a1.x, a1.y, a1.z, a1.w};
#pragma unroll
            for (int i = 0; i < 8; i++) {
                u64 ad = pack2(av[i], av[i]);
                acc[i][0] = ffma2(ad, b0, acc[i][0]);
                acc[i][1] = ffma2(ad, b1, acc[i][1]);
                acc[i][2] = ffma2(ad, b2, acc[i][2]);
                acc[i][3] = ffma2(ad, b3, acc[i][3]);
            }
        }
        __syncthreads();
        if (kt + 1 < KT) {
            const int d = s ^ 1;
#pragma unroll
            for (int l = 0; l < 2; l++) {
                int fid = tid + l * 256;
                int ar = fid >> 2, ac = fid & 3;
                As[d][ac * 4 + 0][ar] = ra[l].x; As[d][ac * 4 + 1][ar] = ra[l].y;
                As[d][ac * 4 + 2][ar] = ra[l].z; As[d][ac * 4 + 3][ar] = ra[l].w;
                int br = fid >> 5, bc = fid & 31;
                *(float4*)&Bs[d][br][bc * 4] = rb[l];
            }
            __syncthreads();
        }
    }

#pragma unroll
    for (int i = 0; i < 8; i++) {
        int row = m0 + tm * 8 + i;
        float* cp = C + (size_t)row * ldc + n0 + tn * 8;
#pragma unroll
        for (int jp = 0; jp < 4; jp++) {
            float lo, hi; unpack2(acc[i][jp], lo, hi);
            if (bias) {
                lo += bias[n0 + tn * 8 + jp * 2];
                hi += bias[n0 + tn * 8 + jp * 2 + 1];
            }
            *(float2*)(cp + jp * 2) = make_float2(lo, hi);
        }
    }
}

// ---------------- zero G ------------------------------------------------------
#define NG4 ((B_ * C_ * C_) / 4)
__global__ void zeroG_kernel()
{
    size_t i = (size_t)blockIdx.x * 256 + threadIdx.x;
    *(float4*)(g_G + i * 4) = make_float4(0.f, 0.f, 0.f, 0.f);
}

// ---------------- Gram: G_b = x_b^T x_b, lower-tri tiles + mirror, k-split 4 -
#define GRAM_KSPLIT 4
#define GRAM_KLEN (N_ / GRAM_KSPLIT)

__global__ void __launch_bounds__(256, 2)
gram_kernel(const float* __restrict__ x)
{
    int i = 0, rem = blockIdx.x;
    while (rem > i) { rem -= i + 1; i++; }
    const int j = rem;
    const int b = blockIdx.y, kz = blockIdx.z;
    const float* xb = x + ((size_t)b * N_ + (size_t)kz * GRAM_KLEN) * C_;

    __shared__ float As[2][16][128];
    __shared__ float Bs[2][16][128];

    const int tid = threadIdx.x;
    const int tm = tid & 15, tn = tid >> 4;

    u64 acc[8][4];
#pragma unroll
    for (int q = 0; q < 8; q++)
#pragma unroll
        for (int p = 0; p < 4; p++) acc[q][p] = pack2(0.f, 0.f);

    float4 ra[2], rb[2];

    auto ldg = [&](int kt) {
#pragma unroll
        for (int l = 0; l < 2; l++) {
            int fid = tid + l * 256;
            int r = fid >> 5, cc = fid & 31;
            const float* src = xb + (size_t)(kt * 16 + r) * C_ + cc * 4;
            ra[l] = *(const float4*)(src + i * 128);
            rb[l] = *(const float4*)(src + j * 128);
        }
    };
    auto sts = [&](int s) {
#pragma unroll
        for (int l = 0; l < 2; l++) {
            int fid = tid + l * 256;
            int r = fid >> 5, cc = fid & 31;
            *(float4*)&As[s][r][cc * 4] = ra[l];
            *(float4*)&Bs[s][r][cc * 4] = rb[l];
        }
    };

    ldg(0); sts(0);
    __syncthreads();

    const int KT = GRAM_KLEN / 16;
    for (int kt = 0; kt < KT; ++kt) {
        const int s = kt & 1;
        if (kt + 1 < KT) ldg(kt + 1);
#pragma unroll
        for (int k = 0; k < 16; k++) {
            float4 a0 = *(const float4*)&As[s][k][tm * 8];
            float4 a1 = *(const float4*)&As[s][k][tm * 8 + 4];
            u64 b0 = *(const u64*)&Bs[s][k][tn * 8 + 0];
            u64 b1 = *(const u64*)&Bs[s][k][tn * 8 + 2];
            u64 b2 = *(const u64*)&Bs[s][k][tn * 8 + 4];
            u64 b3 = *(const u64*)&Bs[s][k][tn * 8 + 6];
            float av[8] = {a0.x, a0.y, a0.z, a0.w, a1.x, a1.y, a1.z, a1.w};
#pragma unroll
            for (int q = 0; q < 8; q++) {
                u64 ad = pack2(av[q], av[q]);
                acc[q][0] = ffma2(ad, b0, acc[q][0]);
                acc[q][1] = ffma2(ad, b1, acc[q][1]);
                acc[q][2] = ffma2(ad, b2, acc[q][2]);
                acc[q][3] = ffma2(ad, b3, acc[q][3]);
            }
        }
        __syncthreads();
        if (kt + 1 < KT) {
            sts(s ^ 1);
            __syncthreads();
        }
    }

    float* Gb = g_G + (size_t)b * C_ * C_;
#pragma unroll
    for (int q = 0; q < 8; q++) {
        int gi = i * 128 + tm * 8 + q;
#pragma unroll
        for (int p = 0; p < 4; p++) {
            float lo, hi; unpack2(acc[q][p], lo, hi);
            int gj = j * 128 + tn * 8 + 2 * p;
            atomicAdd(&Gb[(size_t)gi * C_ + gj], lo);
            atomicAdd(&Gb[(size_t)gi * C_ + gj + 1], hi);
            if (i != j) {
                atomicAdd(&Gb[(size_t)gj * C_ + gi], lo);
                atomicAdd(&Gb[(size_t)(gj + 1) * C_ + gi], hi);
            }
        }
    }
}

// ---------------- diag norms: rn[b,c] = 1/max(sqrt(<W[:,c],T_b[:,c]>),eps) ---
__global__ void diagnorm_kernel(const float* __restrict__ Wqkv)
{
    const int b = blockIdx.y;
    const int lane = threadIdx.x & 31;
    const int w = threadIdx.x >> 5;
    const int c = blockIdx.x * 32 + lane;
    const float* T = g_T + (size_t)b * C_ * (2 * C_);

    float s0 = 0.f, s1 = 0.f, s2 = 0.f, s3 = 0.f;
    for (int r0 = w * 4; r0 < C_; r0 += 32) {
        s0 += Wqkv[(size_t)(r0 + 0) * QKV_COLS + c] * T[(size_t)(r0 + 0) * (2 * C_) + c];
        s1 += Wqkv[(size_t)(r0 + 1) * QKV_COLS + c] * T[(size_t)(r0 + 1) * (2 * C_) + c];
        s2 += Wqkv[(size_t)(r0 + 2) * QKV_COLS + c] * T[(size_t)(r0 + 2) * (2 * C_) + c];
        s3 += Wqkv[(size_t)(r0 + 3) * QKV_COLS + c] * T[(size_t)(r0 + 3) * (2 * C_) + c];
    }
    __shared__ float red[8][32];
    red[w][lane] = (s0 + s1) + (s2 + s3);
    __syncthreads();
    if (w == 0) {
        float t = 0.f;
#pragma unroll
        for (int r = 0; r < 8; r++) t += red[r][lane];
        g_rn[b * (2 * C_) + c] = 1.f / fmaxf(sqrtf(t), 1e-12f);
    }
}

// ---------------- S partials: g_S6[kc][bh] = Wq_h^T Tk_bh over K chunk -------
__global__ void __launch_bounds__(256)
s_kernel(const float* __restrict__ Wqkv)
{
    const int bh = blockIdx.x, b = bh >> 3, h = bh & 7;
    const int kc = blockIdx.y;
    const int tid = threadIdx.x;
    const int te = tid & 15, td = tid >> 4;

    __shared__ float qs[32][96];
    __shared__ float ks[32][96];

    u64 acc2[6][3];
#pragma unroll
    for (int q = 0; q < 6; q++)
#pragma unroll
        for (int p = 0; p < 3; p++) acc2[q][p] = pack2(0.f, 0.f);

    const float* Wq = Wqkv + h * HD;
    const float* Tk = g_T + (size_t)b * C_ * (2 * C_) + C_ + h * HD;

    for (int t = kc * 4; t < kc * 4 + 4; t++) {
#pragma unroll
        for (int l = 0; l < 3; l++) {
            int fid = tid + l * 256;
            int r = fid / 24, cc = fid % 24;
            *(float4*)&qs[r][cc * 4] =
                *(const float4*)(Wq + (size_t)(t * 32 + r) * QKV_COLS + cc * 4);
            *(float4*)&ks[r][cc * 4] =
                *(const float4*)(Tk + (size_t)(t * 32 + r) * (2 * C_) + cc * 4);
        }
        __syncthreads();
#pragma unroll 4
        for (int r = 0; r < 32; r++) {
            const u64* bp = (const u64*)&ks[r][te * 6];
            u64 b0 = bp[0], b1 = bp[1], b2 = bp[2];
#pragma unroll
            for (int q = 0; q < 6; q++) {
                float a = qs[r][td * 6 + q];
                u64 ad = pack2(a, a);
                acc2[q][0] = ffma2(ad, b0, acc2[q][0]);
                acc2[q][1] = ffma2(ad, b1, acc2[q][1]);
                acc2[q][2] = ffma2(ad, b2, acc2[q][2]);
            }
        }
        __syncthreads();
    }
    float* Sp = g_S6 + ((size_t)kc * (B_ * H_) + bh) * HD * HD;
#pragma unroll
    for (int q = 0; q < 6; q++)
#pragma unroll
        for (int p = 0; p < 3; p++) {
            float lo, hi; unpack2(acc2[q][p], lo, hi);
            *(float2*)&Sp[(td * 6 + q) * HD + te * 6 + 2 * p] = make_float2(lo, hi);
        }
}

// ---------------- sum partials + scale + softmax -> g_S ----------------------
__global__ void softmax_kernel(const float* __restrict__ temp)
{
    const int bh = blockIdx.x, b = bh >> 3, h = bh & 7;
    const int d = threadIdx.x;
    if (d >= HD) return;
    const float rq = g_rn[b * (2 * C_) + h * HD + d] * temp[h];
    const float* rk = g_rn + b * (2 * C_) + C_ + h * HD;
    const size_t rowoff = (size_t)bh * HD * HD + (size_t)d * HD;

    float vals[HD];
    float m = -1e30f;
    for (int e = 0; e < HD; e++) {
        float v = 0.f;
#pragma unroll
        for (int k = 0; k < SKC; k++)
            v += g_S6[(size_t)k * (B_ * H_ * HD * HD) + rowoff + e];
        v *= rq * rk[e];
        vals[e] = v;
        if (v > m) m = v;
    }
    float ssum = 0.f;
    for (int e = 0; e < HD; e++) {
        float v = expf(vals[e] - m);
        vals[e] = v;
        ssum += v;
    }
    float inv = 1.f / ssum;
    float* row = g_S + rowoff;
    for (int e = 0; e < HD; e++) row[e] = vals[e] * inv;
}

// ---------------- P_b[h*96+e, j] = sum_d attn_bh[d,e] * Wproj[h*96+d, j] -----
__global__ void __launch_bounds__(256)
p_kernel(const float* __restrict__ Wproj)
{
    const int bh = blockIdx.x, b = bh >> 3, h = bh & 7;
    const int jt = blockIdx.y;
    const int tid = threadIdx.x;
    const int er = tid >> 5, lane = tid & 31;

    __shared__ float ats[32][96];
    __shared__ float ws[32][128];

    u64 acc2[12][2];
#pragma unroll
    for (int q = 0; q < 12; q++) { acc2[q][0] = pack2(0.f, 0.f); acc2[q][1] = pack2(0.f, 0.f); }

    const float* Sp = g_S + (size_t)bh * HD * HD;
    const float* Wp = Wproj + (size_t)(h * HD) * C_ + jt * 128;

    for (int dc = 0; dc < 3; dc++) {
        __syncthreads();
#pragma unroll
        for (int l = 0; l < 3; l++) {
            int fid = tid + l * 256;
            int r = fid / 24, cc = fid % 24;
            *(float4*)&ats[r][cc * 4] = *(const float4*)(Sp + (size_t)(dc * 32 + r) * HD + cc * 4);
        }
#pragma unroll
        for (int l = 0; l < 4; l++) {
            int fid = tid + l * 256;
            int r = fid >> 5, cc = fid & 31;
            *(float4*)&ws[r][cc * 4] = *(const float4*)(Wp + (size_t)(dc * 32 + r) * C_ + cc * 4);
        }
        __syncthreads();
#pragma unroll 4
        for (int d = 0; d < 32; d++) {
            u64 w01 = *(const u64*)&ws[d][lane * 4];
            u64 w23 = *(const u64*)&ws[d][lane * 4 + 2];
#pragma unroll
            for (int q = 0; q < 12; q++) {
                float a = ats[d][er * 12 + q];
                u64 ad = pack2(a, a);
                acc2[q][0] = ffma2(ad, w01, acc2[q][0]);
                acc2[q][1] = ffma2(ad, w23, acc2[q][1]);
            }
        }
    }

    float* Pb = g_P + (size_t)b * C_ * C_;
#pragma unroll
    for (int q = 0; q < 12; q++) {
        float f0, f1, f2, f3;
        unpack2(acc2[q][0], f0, f1);
        unpack2(acc2[q][1], f2, f3);
        *(float4*)&Pb[(size_t)(h * HD + er * 12 + q) * C_ + jt * 128 + lane * 4] =
            make_float4(f0, f1, f2, f3);
    }
}

// ---------------- launch ----------------------------------------------------
extern "C" void kernel_launch(void* const* d_in, const int* in_sizes, int n_in,
                              void* d_out, int out_size)
{
    const float* x     = (const float*)d_in[0];
    const float* Wqkv  = (const float*)d_in[1];
    const float* temp  = (const float*)d_in[2];
    const float* Wproj = (const float*)d_in[3];
    const float* bproj = (const float*)d_in[4];
    float* out = (float*)d_out;

    static float *dG = nullptr, *dT = nullptr, *dP = nullptr, *dQ = nullptr;
    static cudaStream_t s1 = nullptr;
    static cudaEvent_t evT = nullptr, evD = nullptr;
    if (!dG) {
        cudaGetSymbolAddress((void**)&dG, g_G);
        cudaGetSymbolAddress((void**)&dT, g_T);
        cudaGetSymbolAddress((void**)&dP, g_P);
        cudaGetSymbolAddress((void**)&dQ, g_Q);
        cudaStreamCreateWithFlags(&s1, cudaStreamNonBlocking);
        cudaEventCreateWithFlags(&evT, cudaEventDisableTiming);
        cudaEventCreateWithFlags(&evD, cudaEventDisableTiming);
    }

    // 1) zero G, then G_b = x_b^T x_b (lower tiles + mirror, k-split 4)
    zeroG_kernel<<<NG4 / 256, 256>>>();
    gram_kernel<<<dim3(21, B_, GRAM_KSPLIT), 256>>>(x);

    // 2) T_b = G_b @ [Wq|Wk]
    sgemm_kernel<<<dim3((2 * C_) / 128, C_ / 128, B_), 256>>>(
        dG, Wqkv, dT, nullptr, C_, C_, QKV_COLS, 2 * C_,
        (long long)C_ * C_, (long long)C_ * 2 * C_, 0, 0);

    // 3) fork: diagnorm on side stream, s partials on main stream (both read T)
    cudaEventRecord(evT, 0);
    cudaStreamWaitEvent(s1, evT, 0);
    diagnorm_kernel<<<dim3((2 * C_) / 32, B_), 256, 0, s1>>>(Wqkv);
    cudaEventRecord(evD, s1);

    s_kernel<<<dim3(B_ * H_, SKC), 256>>>(Wqkv);

    // join, then softmax (needs s partials + norms)
    cudaStreamWaitEvent(0, evD, 0);
    softmax_kernel<<<B_ * H_, 96>>>(temp);

    // 4) P_b = attn^T-blocks @ Wproj
    p_kernel<<<dim3(B_ * H_, C_ / 128), 256>>>(Wproj);

    // 5) Q_b = Wv @ P_b  (batched over B; Wv = cols [2C,3C) of Wqkv)
    sgemm_kernel<<<dim3(C_ / 128, C_ / 128, B_), 256>>>(
        Wqkv + 2 * C_, dP, dQ, nullptr, C_, QKV_COLS, C_, C_,
        0, (long long)C_ * C_, (long long)C_ * C_, 0);

    // 6) out = x @ Q_b + bproj  (Q selected per 4096-row batch block)
    sgemm_kernel<<<dim3(C_ / 128, M_ / 128, 1), 256>>>(
        x, dQ, out, bproj, C_, C_, C_, C_, 0, 0, 0, (long long)C_ * C_);
}

// round 13
// speedup vs baseline: 1.1006x; 1.0339x over previous
#include <cuda_runtime.h>
#include <math.h>
#include <stdint.h>

#define B_ 8
#define N_ 4096
#define C_ 768
#define H_ 8
#define HD 96
#define M_ (B_*N_)        // 32768 rows
#define QKV_COLS (3*C_)   // 2304
#define SKC 6             // s_kernel K-split
#define GB 4              // batches per group

// ---------------- scratch (device globals: allocation-free) ----------------
__device__ __align__(128) float g_G[(size_t)B_ * C_ * C_];        // x^T x per batch
__device__ __align__(128) float g_T[(size_t)B_ * C_ * 2 * C_];    // G @ [Wq|Wk]
__device__ __align__(128) float g_P[(size_t)B_ * C_ * C_];        // attn^T @ Wproj
__device__ __align__(128) float g_Q[(size_t)B_ * C_ * C_];        // Wv @ P_b
__device__ __align__(128) float g_S[B_ * H_ * HD * HD];           // attn (post-softmax)
__device__ __align__(128) float g_S6[SKC * B_ * H_ * HD * HD];    // logit partials
__device__ __align__(128) float g_rn[B_ * 2 * C_];                // 1/max(||col||,eps)

// ---------------- packed fp32x2 helpers (FFMA2 path) ------------------------
typedef unsigned long long u64;
__device__ __forceinline__ u64 pack2(float lo, float hi) {
    u64 r; asm("mov.b64 %0, {%1,%2};" : "=l"(r) : "f"(lo), "f"(hi)); return r;
}
__device__ __forceinline__ void unpack2(u64 v, float& lo, float& hi) {
    asm("mov.b64 {%0,%1}, %2;" : "=f"(lo), "=f"(hi) : "l"(v));
}
__device__ __forceinline__ u64 ffma2(u64 a, u64 b, u64 c) {
    u64 d; asm("fma.rn.f32x2 %0, %1, %2, %3;" : "=l"(d) : "l"(a), "l"(b), "l"(c)); return d;
}

// ---------------- generic SGEMM 128x128 (T, Q, out) --------------------------
// Two-sync double-buffered mainloop (proven fastest config; byte-identical).
__global__ void __launch_bounds__(256, 2)
sgemm_kernel(const float* __restrict__ A, const float* __restrict__ Bm,
             float* __restrict__ C, const float* __restrict__ bias,
             int K, int lda, int ldb, int ldc,
             long long sAz, long long sCz, long long sBz, long long sBm)
{
    const int bz = blockIdx.z;
    const int m0 = blockIdx.y * 128, n0 = blockIdx.x * 128;
    A  += (size_t)bz * sAz;
    C  += (size_t)bz * sCz;
    Bm += (size_t)bz * sBz + (size_t)(m0 >> 12) * sBm;

    __shared__ float As[2][16][128];
    __shared__ float Bs[2][16][128];

    const int tid = threadIdx.x;
    const int tm = tid & 15, tn = tid >> 4;

    u64 acc[8][4];
#pragma unroll
    for (int i = 0; i < 8; i++)
#pragma unroll
        for (int j = 0; j < 4; j++) acc[i][j] = pack2(0.f, 0.f);

    float4 ra[2], rb[2];
#pragma unroll
    for (int l = 0; l < 2; l++) {
        int fid = tid + l * 256;
        int ar = fid >> 2, ac = fid & 3;
        ra[l] = *(const float4*)(A + (size_t)(m0 + ar) * lda + ac * 4);
        int br = fid >> 5, bc = fid & 31;
        rb[l] = *(const float4*)(Bm + (size_t)br * ldb + n0 + bc * 4);
    }
#pragma unroll
    for (int l = 0; l < 2; l++) {
        int fid = tid + l * 256;
        int ar = fid >> 2, ac = fid & 3;
        As[0][ac * 4 + 0][ar] = ra[l].x; As[0][ac * 4 + 1][ar] = ra[l].y;
        As[0][ac * 4 + 2][ar] = ra[l].z; As[0][ac * 4 + 3][ar] = ra[l].w;
        int br = fid >> 5, bc = fid & 31;
        *(float4*)&Bs[0][br][bc * 4] = rb[l];
    }
    __syncthreads();

    const int KT = K >> 4;
    for (int kt = 0; kt < KT; ++kt) {
        const int s = kt & 1;
        if (kt + 1 < KT) {
            int k0 = (kt + 1) << 4;
#pragma unroll
            for (int l = 0; l < 2; l++) {
                int fid = tid + l * 256;
                int ar = fid >> 2, ac = fid & 3;
                ra[l] = *(const float4*)(A + (size_t)(m0 + ar) * lda + k0 + ac * 4);
                int br = fid >> 5, bc = fid & 31;
                rb[l] = *(const float4*)(Bm + (size_t)(k0 + br) * ldb + n0 + bc * 4);
            }
        }
#pragma unroll
        for (int k = 0; k < 16; k++) {
            float4 a0 = *(const float4*)&As[s][k][tm * 8];
            float4 a1 = *(const float4*)&As[s][k][tm * 8 + 4];
            u64 b0 = *(const u64*)&Bs[s][k][tn * 8 + 0];
            u64 b1 = *(const u64*)&Bs[s][k][tn * 8 + 2];
            u64 b2 = *(const u64*)&Bs[s][k][tn * 8 + 4];
            u64 b3 = *(const u64*)&Bs[s][k][tn * 8 + 6];
            float av[8] = {a0.x, a0.y, a0.z, a0.w, a1.x, a1.y, a1.z, a1.w};
#pragma unroll
            for (int i = 0; i < 8; i++) {
                u64 ad = pack2(av[i], av[i]);
                acc[i][0] = ffma2(ad, b0, acc[i][0]);
                acc[i][1] = ffma2(ad, b1, acc[i][1]);
                acc[i][2] = ffma2(ad, b2, acc[i][2]);
                acc[i][3] = ffma2(ad, b3, acc[i][3]);
            }
        }
        __syncthreads();
        if (kt + 1 < KT) {
            const int d = s ^ 1;
#pragma unroll
            for (int l = 0; l < 2; l++) {
                int fid = tid + l * 256;
                int ar = fid >> 2, ac = fid & 3;
                As[d][ac * 4 + 0][ar] = ra[l].x; As[d][ac * 4 + 1][ar] = ra[l].y;
                As[d][ac * 4 + 2][ar] = ra[l].z; As[d][ac * 4 + 3][ar] = ra[l].w;
                int br = fid >> 5, bc = fid & 31;
                *(float4*)&Bs[d][br][bc * 4] = rb[l];
            }
            __syncthreads();
        }
    }

#pragma unroll
    for (int i = 0; i < 8; i++) {
        int row = m0 + tm * 8 + i;
        float* cp = C + (size_t)row * ldc + n0 + tn * 8;
#pragma unroll
        for (int jp = 0; jp < 4; jp++) {
            float lo, hi; unpack2(acc[i][jp], lo, hi);
            if (bias) {
                lo += bias[n0 + tn * 8 + jp * 2];
                hi += bias[n0 + tn * 8 + jp * 2 + 1];
            }
            *(float2*)(cp + jp * 2) = make_float2(lo, hi);
        }
    }
}

// ---------------- zero G (per group) ------------------------------------------
#define NG4G ((GB * C_ * C_) / 4)
__global__ void zeroG_kernel(int b0)
{
    size_t i = (size_t)blockIdx.x * 256 + threadIdx.x;
    *(float4*)(g_G + (size_t)b0 * C_ * C_ + i * 4) = make_float4(0.f, 0.f, 0.f, 0.f);
}

// ---------------- Gram: G_b = x_b^T x_b, lower-tri tiles + mirror, k-split 4 -
#define GRAM_KSPLIT 4
#define GRAM_KLEN (N_ / GRAM_KSPLIT)

__global__ void __launch_bounds__(256, 2)
gram_kernel(const float* __restrict__ x, int b0)
{
    int i = 0, rem = blockIdx.x;
    while (rem > i) { rem -= i + 1; i++; }
    const int j = rem;
    const int b = b0 + blockIdx.y, kz = blockIdx.z;
    const float* xb = x + ((size_t)b * N_ + (size_t)kz * GRAM_KLEN) * C_;

    __shared__ float As[2][16][128];
    __shared__ float Bs[2][16][128];

    const int tid = threadIdx.x;
    const int tm = tid & 15, tn = tid >> 4;

    u64 acc[8][4];
#pragma unroll
    for (int q = 0; q < 8; q++)
#pragma unroll
        for (int p = 0; p < 4; p++) acc[q][p] = pack2(0.f, 0.f);

    float4 ra[2], rb[2];

    auto ldg = [&](int kt) {
#pragma unroll
        for (int l = 0; l < 2; l++) {
            int fid = tid + l * 256;
            int r = fid >> 5, cc = fid & 31;
            const float* src = xb + (size_t)(kt * 16 + r) * C_ + cc * 4;
            ra[l] = *(const float4*)(src + i * 128);
            rb[l] = *(const float4*)(src + j * 128);
        }
    };
    auto sts = [&](int s) {
#pragma unroll
        for (int l = 0; l < 2; l++) {
            int fid = tid + l * 256;
            int r = fid >> 5, cc = fid & 31;
            *(float4*)&As[s][r][cc * 4] = ra[l];
            *(float4*)&Bs[s][r][cc * 4] = rb[l];
        }
    };

    ldg(0); sts(0);
    __syncthreads();

    const int KT = GRAM_KLEN / 16;
    for (int kt = 0; kt < KT; ++kt) {
        const int s = kt & 1;
        if (kt + 1 < KT) ldg(kt + 1);
#pragma unroll
        for (int k = 0; k < 16; k++) {
            float4 a0 = *(const float4*)&As[s][k][tm * 8];
            float4 a1 = *(const float4*)&As[s][k][tm * 8 + 4];
            u64 b0r = *(const u64*)&Bs[s][k][tn * 8 + 0];
            u64 b1 = *(const u64*)&Bs[s][k][tn * 8 + 2];
            u64 b2 = *(const u64*)&Bs[s][k][tn * 8 + 4];
            u64 b3 = *(const u64*)&Bs[s][k][tn * 8 + 6];
            float av[8] = {a0.x, a0.y, a0.z, a0.w, a1.x, a1.y, a1.z, a1.w};
#pragma unroll
            for (int q = 0; q < 8; q++) {
                u64 ad = pack2(av[q], av[q]);
                acc[q][0] = ffma2(ad, b0r, acc[q][0]);
                acc[q][1] = ffma2(ad, b1, acc[q][1]);
                acc[q][2] = ffma2(ad, b2, acc[q][2]);
                acc[q][3] = ffma2(ad, b3, acc[q][3]);
            }
        }
        __syncthreads();
        if (kt + 1 < KT) {
            sts(s ^ 1);
            __syncthreads();
        }
    }

    float* Gb = g_G + (size_t)b * C_ * C_;
#pragma unroll
    for (int q = 0; q < 8; q++) {
        int gi = i * 128 + tm * 8 + q;
#pragma unroll
        for (int p = 0; p < 4; p++) {
            float lo, hi; unpack2(acc[q][p], lo, hi);
            int gj = j * 128 + tn * 8 + 2 * p;
            atomicAdd(&Gb[(size_t)gi * C_ + gj], lo);
            atomicAdd(&Gb[(size_t)gi * C_ + gj + 1], hi);
            if (i != j) {
                atomicAdd(&Gb[(size_t)gj * C_ + gi], lo);
                atomicAdd(&Gb[(size_t)(gj + 1) * C_ + gi], hi);
            }
        }
    }
}

// ---------------- diag norms --------------------------------------------------
__global__ void diagnorm_kernel(const float* __restrict__ Wqkv, int b0)
{
    const int b = b0 + blockIdx.y;
    const int lane = threadIdx.x & 31;
    const int w = threadIdx.x >> 5;
    const int c = blockIdx.x * 32 + lane;
    const float* T = g_T + (size_t)b * C_ * (2 * C_);

    float s0 = 0.f, s1 = 0.f, s2 = 0.f, s3 = 0.f;
    for (int r0 = w * 4; r0 < C_; r0 += 32) {
        s0 += Wqkv[(size_t)(r0 + 0) * QKV_COLS + c] * T[(size_t)(r0 + 0) * (2 * C_) + c];
        s1 += Wqkv[(size_t)(r0 + 1) * QKV_COLS + c] * T[(size_t)(r0 + 1) * (2 * C_) + c];
        s2 += Wqkv[(size_t)(r0 + 2) * QKV_COLS + c] * T[(size_t)(r0 + 2) * (2 * C_) + c];
        s3 += Wqkv[(size_t)(r0 + 3) * QKV_COLS + c] * T[(size_t)(r0 + 3) * (2 * C_) + c];
    }
    __shared__ float red[8][32];
    red[w][lane] = (s0 + s1) + (s2 + s3);
    __syncthreads();
    if (w == 0) {
        float t = 0.f;
#pragma unroll
        for (int r = 0; r < 8; r++) t += red[r][lane];
        g_rn[b * (2 * C_) + c] = 1.f / fmaxf(sqrtf(t), 1e-12f);
    }
}

// ---------------- S partials: g_S6[kc][bh] = Wq_h^T Tk_bh over K chunk -------
__global__ void __launch_bounds__(256)
s_kernel(const float* __restrict__ Wqkv, int bh0)
{
    const int bh = bh0 + blockIdx.x, b = bh >> 3, h = bh & 7;
    const int kc = blockIdx.y;
    const int tid = threadIdx.x;
    const int te = tid & 15, td = tid >> 4;

    __shared__ float qs[32][96];
    __shared__ float ks[32][96];

    u64 acc2[6][3];
#pragma unroll
    for (int q = 0; q < 6; q++)
#pragma unroll
        for (int p = 0; p < 3; p++) acc2[q][p] = pack2(0.f, 0.f);

    const float* Wq = Wqkv + h * HD;
    const float* Tk = g_T + (size_t)b * C_ * (2 * C_) + C_ + h * HD;

    for (int t = kc * 4; t < kc * 4 + 4; t++) {
#pragma unroll
        for (int l = 0; l < 3; l++) {
            int fid = tid + l * 256;
            int r = fid / 24, cc = fid % 24;
            *(float4*)&qs[r][cc * 4] =
                *(const float4*)(Wq + (size_t)(t * 32 + r) * QKV_COLS + cc * 4);
            *(float4*)&ks[r][cc * 4] =
                *(const float4*)(Tk + (size_t)(t * 32 + r) * (2 * C_) + cc * 4);
        }
        __syncthreads();
#pragma unroll 4
        for (int r = 0; r < 32; r++) {
            const u64* bp = (const u64*)&ks[r][te * 6];
            u64 b0 = bp[0], b1 = bp[1], b2 = bp[2];
#pragma unroll
            for (int q = 0; q < 6; q++) {
                float a = qs[r][td * 6 + q];
                u64 ad = pack2(a, a);
                acc2[q][0] = ffma2(ad, b0, acc2[q][0]);
                acc2[q][1] = ffma2(ad, b1, acc2[q][1]);
                acc2[q][2] = ffma2(ad, b2, acc2[q][2]);
            }
        }
        __syncthreads();
    }
    float* Sp = g_S6 + ((size_t)kc * (B_ * H_) + bh) * HD * HD;
#pragma unroll
    for (int q = 0; q < 6; q++)
#pragma unroll
        for (int p = 0; p < 3; p++) {
            float lo, hi; unpack2(acc2[q][p], lo, hi);
            *(float2*)&Sp[(td * 6 + q) * HD + te * 6 + 2 * p] = make_float2(lo, hi);
        }
}

// ---------------- sum partials + scale + softmax -> g_S ----------------------
__global__ void softmax_kernel(const float* __restrict__ temp, int bh0)
{
    const int bh = bh0 + blockIdx.x, b = bh >> 3, h = bh & 7;
    const int d = threadIdx.x;
    if (d >= HD) return;
    const float rq = g_rn[b * (2 * C_) + h * HD + d] * temp[h];
    const float* rk = g_rn + b * (2 * C_) + C_ + h * HD;
    const size_t rowoff = (size_t)bh * HD * HD + (size_t)d * HD;

    float vals[HD];
    float m = -1e30f;
    for (int e = 0; e < HD; e++) {
        float v = 0.f;
#pragma unroll
        for (int k = 0; k < SKC; k++)
            v += g_S6[(size_t)k * (B_ * H_ * HD * HD) + rowoff + e];
        v *= rq * rk[e];
        vals[e] = v;
        if (v > m) m = v;
    }
    float ssum = 0.f;
    for (int e = 0; e < HD; e++) {
        float v = expf(vals[e] - m);
        vals[e] = v;
        ssum += v;
    }
    float inv = 1.f / ssum;
    float* row = g_S + rowoff;
    for (int e = 0; e < HD; e++) row[e] = vals[e] * inv;
}

// ---------------- P_b[h*96+e, j] = sum_d attn_bh[d,e] * Wproj[h*96+d, j] -----
__global__ void __launch_bounds__(256)
p_kernel(const float* __restrict__ Wproj, int bh0)
{
    const int bh = bh0 + blockIdx.x, b = bh >> 3, h = bh & 7;
    const int jt = blockIdx.y;
    const int tid = threadIdx.x;
    const int er = tid >> 5, lane = tid & 31;

    __shared__ float ats[32][96];
    __shared__ float ws[32][128];

    u64 acc2[12][2];
#pragma unroll
    for (int q = 0; q < 12; q++) { acc2[q][0] = pack2(0.f, 0.f); acc2[q][1] = pack2(0.f, 0.f); }

    const float* Sp = g_S + (size_t)bh * HD * HD;
    const float* Wp = Wproj + (size_t)(h * HD) * C_ + jt * 128;

    for (int dc = 0; dc < 3; dc++) {
        __syncthreads();
#pragma unroll
        for (int l = 0; l < 3; l++) {
            int fid = tid + l * 256;
            int r = fid / 24, cc = fid % 24;
            *(float4*)&ats[r][cc * 4] = *(const float4*)(Sp + (size_t)(dc * 32 + r) * HD + cc * 4);
        }
#pragma unroll
        for (int l = 0; l < 4; l++) {
            int fid = tid + l * 256;
            int r = fid >> 5, cc = fid & 31;
            *(float4*)&ws[r][cc * 4] = *(const float4*)(Wp + (size_t)(dc * 32 + r) * C_ + cc * 4);
        }
        __syncthreads();
#pragma unroll 4
        for (int d = 0; d < 32; d++) {
            u64 w01 = *(const u64*)&ws[d][lane * 4];
            u64 w23 = *(const u64*)&ws[d][lane * 4 + 2];
#pragma unroll
            for (int q = 0; q < 12; q++) {
                float a = ats[d][er * 12 + q];
                u64 ad = pack2(a, a);
                acc2[q][0] = ffma2(ad, w01, acc2[q][0]);
                acc2[q][1] = ffma2(ad, w23, acc2[q][1]);
            }
        }
    }

    float* Pb = g_P + (size_t)b * C_ * C_;
#pragma unroll
    for (int q = 0; q < 12; q++) {
        float f0, f1, f2, f3;
        unpack2(acc2[q][0], f0, f1);
        unpack2(acc2[q][1], f2, f3);
        *(float4*)&Pb[(size_t)(h * HD + er * 12 + q) * C_ + jt * 128 + lane * 4] =
            make_float4(f0, f1, f2, f3);
    }
}

// ---------------- per-group chain --------------------------------------------
static void launch_group(int g, cudaStream_t st,
                         const float* x, const float* Wqkv, const float* temp,
                         const float* Wproj, const float* bproj, float* out,
                         float* dG, float* dT, float* dP, float* dQ)
{
    const int b0 = g * GB;
    const long long CC = (long long)C_ * C_;

    zeroG_kernel<<<NG4G / 256, 256, 0, st>>>(b0);
    gram_kernel<<<dim3(21, GB, GRAM_KSPLIT), 256, 0, st>>>(x, b0);

    // T_b = G_b @ [Wq|Wk]
    sgemm_kernel<<<dim3((2 * C_) / 128, C_ / 128, GB), 256, 0, st>>>(
        dG + (size_t)b0 * CC, Wqkv, dT + (size_t)b0 * C_ * 2 * C_, nullptr,
        C_, C_, QKV_COLS, 2 * C_, CC, (long long)C_ * 2 * C_, 0, 0);

    s_kernel<<<dim3(GB * H_, SKC), 256, 0, st>>>(Wqkv, b0 * H_);
    diagnorm_kernel<<<dim3((2 * C_) / 32, GB), 256, 0, st>>>(Wqkv, b0);
    softmax_kernel<<<GB * H_, 96, 0, st>>>(temp, b0 * H_);
    p_kernel<<<dim3(GB * H_, C_ / 128), 256, 0, st>>>(Wproj, b0 * H_);

    // Q_b = Wv @ P_b
    sgemm_kernel<<<dim3(C_ / 128, C_ / 128, GB), 256, 0, st>>>(
        Wqkv + 2 * C_, dP + (size_t)b0 * CC, dQ + (size_t)b0 * CC, nullptr,
        C_, QKV_COLS, C_, C_, 0, CC, CC, 0);

    // out rows [b0*N, (b0+GB)*N) = x @ Q_b + bproj
    sgemm_kernel<<<dim3(C_ / 128, (GB * N_) / 128, 1), 256, 0, st>>>(
        x + (size_t)b0 * N_ * C_, dQ + (size_t)b0 * CC,
        out + (size_t)b0 * N_ * C_, bproj,
        C_, C_, C_, C_, 0, 0, 0, CC);
}

// ---------------- launch ----------------------------------------------------
extern "C" void kernel_launch(void* const* d_in, const int* in_sizes, int n_in,
                              void* d_out, int out_size)
{
    const float* x     = (const float*)d_in[0];
    const float* Wqkv  = (const float*)d_in[1];
    const float* temp  = (const float*)d_in[2];
    const float* Wproj = (const float*)d_in[3];
    const float* bproj = (const float*)d_in[4];
    float* out = (float*)d_out;

    static float *dG = nullptr, *dT = nullptr, *dP = nullptr, *dQ = nullptr;
    static cudaStream_t s1 = nullptr;
    static cudaEvent_t ev0 = nullptr, evB = nullptr;
    if (!dG) {
        cudaGetSymbolAddress((void**)&dG, g_G);
        cudaGetSymbolAddress((void**)&dT, g_T);
        cudaGetSymbolAddress((void**)&dP, g_P);
        cudaGetSymbolAddress((void**)&dQ, g_Q);
        cudaStreamCreateWithFlags(&s1, cudaStreamNonBlocking);
        cudaEventCreateWithFlags(&ev0, cudaEventDisableTiming);
        cudaEventCreateWithFlags(&evB, cudaEventDisableTiming);
    }

    // fork: group B onto side stream
    cudaEventRecord(ev0, 0);
    cudaStreamWaitEvent(s1, ev0, 0);

    launch_group(1, s1, x, Wqkv, temp, Wproj, bproj, out, dG, dT, dP, dQ);  // batches 4-7
    launch_group(0, 0,  x, Wqkv, temp, Wproj, bproj, out, dG, dT, dP, dQ);  // batches 0-3

    // join
    cudaEventRecord(evB, s1);
    cudaStreamWaitEvent(0, evB, 0);
}

// round 14
// speedup vs baseline: 1.1356x; 1.0318x over previous
#include <cuda_runtime.h>
#include <math.h>
#include <stdint.h>

#define B_ 8
#define N_ 4096
#define C_ 768
#define H_ 8
#define HD 96
#define M_ (B_*N_)        // 32768 rows
#define QKV_COLS (3*C_)   // 2304
#define SKC 6             // s_kernel K-split
#define GB 2              // batches per group
#define NGRP (B_ / GB)    // 4 groups

// ---------------- scratch (device globals: allocation-free) ----------------
__device__ __align__(128) float g_G[(size_t)B_ * C_ * C_];        // x^T x per batch
__device__ __align__(128) float g_T[(size_t)B_ * C_ * 2 * C_];    // G @ [Wq|Wk]
__device__ __align__(128) float g_P[(size_t)B_ * C_ * C_];        // attn^T @ Wproj
__device__ __align__(128) float g_Q[(size_t)B_ * C_ * C_];        // Wv @ P_b
__device__ __align__(128) float g_S[B_ * H_ * HD * HD];           // attn (post-softmax)
__device__ __align__(128) float g_S6[SKC * B_ * H_ * HD * HD];    // logit partials
__device__ __align__(128) float g_rn[B_ * 2 * C_];                // 1/max(||col||,eps)

// ---------------- packed fp32x2 helpers (FFMA2 path) ------------------------
typedef unsigned long long u64;
__device__ __forceinline__ u64 pack2(float lo, float hi) {
    u64 r; asm("mov.b64 %0, {%1,%2};" : "=l"(r) : "f"(lo), "f"(hi)); return r;
}
__device__ __forceinline__ void unpack2(u64 v, float& lo, float& hi) {
    asm("mov.b64 {%0,%1}, %2;" : "=f"(lo), "=f"(hi) : "l"(v));
}
__device__ __forceinline__ u64 ffma2(u64 a, u64 b, u64 c) {
    u64 d; asm("fma.rn.f32x2 %0, %1, %2, %3;" : "=l"(d) : "l"(a), "l"(b), "l"(c)); return d;
}

// ---------------- generic SGEMM 128x128 (T, Q, out) --------------------------
// Two-sync double-buffered mainloop (proven fastest config; byte-identical).
__global__ void __launch_bounds__(256, 2)
sgemm_kernel(const float* __restrict__ A, const float* __restrict__ Bm,
             float* __restrict__ C, const float* __restrict__ bias,
             int K, int lda, int ldb, int ldc,
             long long sAz, long long sCz, long long sBz, long long sBm)
{
    const int bz = blockIdx.z;
    const int m0 = blockIdx.y * 128, n0 = blockIdx.x * 128;
    A  += (size_t)bz * sAz;
    C  += (size_t)bz * sCz;
    Bm += (size_t)bz * sBz + (size_t)(m0 >> 12) * sBm;

    __shared__ float As[2][16][128];
    __shared__ float Bs[2][16][128];

    const int tid = threadIdx.x;
    const int tm = tid & 15, tn = tid >> 4;

    u64 acc[8][4];
#pragma unroll
    for (int i = 0; i < 8; i++)
#pragma unroll
        for (int j = 0; j < 4; j++) acc[i][j] = pack2(0.f, 0.f);

    float4 ra[2], rb[2];
#pragma unroll
    for (int l = 0; l < 2; l++) {
        int fid = tid + l * 256;
        int ar = fid >> 2, ac = fid & 3;
        ra[l] = *(const float4*)(A + (size_t)(m0 + ar) * lda + ac * 4);
        int br = fid >> 5, bc = fid & 31;
        rb[l] = *(const float4*)(Bm + (size_t)br * ldb + n0 + bc * 4);
    }
#pragma unroll
    for (int l = 0; l < 2; l++) {
        int fid = tid + l * 256;
        int ar = fid >> 2, ac = fid & 3;
        As[0][ac * 4 + 0][ar] = ra[l].x; As[0][ac * 4 + 1][ar] = ra[l].y;
        As[0][ac * 4 + 2][ar] = ra[l].z; As[0][ac * 4 + 3][ar] = ra[l].w;
        int br = fid >> 5, bc = fid & 31;
        *(float4*)&Bs[0][br][bc * 4] = rb[l];
    }
    __syncthreads();

    const int KT = K >> 4;
    for (int kt = 0; kt < KT; ++kt) {
        const int s = kt & 1;
        if (kt + 1 < KT) {
            int k0 = (kt + 1) << 4;
#pragma unroll
            for (int l = 0; l < 2; l++) {
                int fid = tid + l * 256;
                int ar = fid >> 2, ac = fid & 3;
                ra[l] = *(const float4*)(A + (size_t)(m0 + ar) * lda + k0 + ac * 4);
                int br = fid >> 5, bc = fid & 31;
                rb[l] = *(const float4*)(Bm + (size_t)(k0 + br) * ldb + n0 + bc * 4);
            }
        }
#pragma unroll
        for (int k = 0; k < 16; k++) {
            float4 a0 = *(const float4*)&As[s][k][tm * 8];
            float4 a1 = *(const float4*)&As[s][k][tm * 8 + 4];
            u64 b0 = *(const u64*)&Bs[s][k][tn * 8 + 0];
            u64 b1 = *(const u64*)&Bs[s][k][tn * 8 + 2];
            u64 b2 = *(const u64*)&Bs[s][k][tn * 8 + 4];
            u64 b3 = *(const u64*)&Bs[s][k][tn * 8 + 6];
            float av[8] = {a0.x, a0.y, a0.z, a0.w, a1.x, a1.y, a1.z, a1.w};
#pragma unroll
            for (int i = 0; i < 8; i++) {
                u64 ad = pack2(av[i], av[i]);
                acc[i][0] = ffma2(ad, b0, acc[i][0]);
                acc[i][1] = ffma2(ad, b1, acc[i][1]);
                acc[i][2] = ffma2(ad, b2, acc[i][2]);
                acc[i][3] = ffma2(ad, b3, acc[i][3]);
            }
        }
        __syncthreads();
        if (kt + 1 < KT) {
            const int d = s ^ 1;
#pragma unroll
            for (int l = 0; l < 2; l++) {
                int fid = tid + l * 256;
                int ar = fid >> 2, ac = fid & 3;
                As[d][ac * 4 + 0][ar] = ra[l].x; As[d][ac * 4 + 1][ar] = ra[l].y;
                As[d][ac * 4 + 2][ar] = ra[l].z; As[d][ac * 4 + 3][ar] = ra[l].w;
                int br = fid >> 5, bc = fid & 31;
                *(float4*)&Bs[d][br][bc * 4] = rb[l];
            }
            __syncthreads();
        }
    }

#pragma unroll
    for (int i = 0; i < 8; i++) {
        int row = m0 + tm * 8 + i;
        float* cp = C + (size_t)row * ldc + n0 + tn * 8;
#pragma unroll
        for (int jp = 0; jp < 4; jp++) {
            float lo, hi; unpack2(acc[i][jp], lo, hi);
            if (bias) {
                lo += bias[n0 + tn * 8 + jp * 2];
                hi += bias[n0 + tn * 8 + jp * 2 + 1];
            }
            *(float2*)(cp + jp * 2) = make_float2(lo, hi);
        }
    }
}

// ---------------- zero G (per group) ------------------------------------------
#define NG4G ((GB * C_ * C_) / 4)
__global__ void zeroG_kernel(int b0)
{
    size_t i = (size_t)blockIdx.x * 256 + threadIdx.x;
    *(float4*)(g_G + (size_t)b0 * C_ * C_ + i * 4) = make_float4(0.f, 0.f, 0.f, 0.f);
}

// ---------------- Gram: G_b = x_b^T x_b, lower-tri tiles + mirror, k-split 4 -
#define GRAM_KSPLIT 4
#define GRAM_KLEN (N_ / GRAM_KSPLIT)

__global__ void __launch_bounds__(256, 2)
gram_kernel(const float* __restrict__ x, int b0)
{
    int i = 0, rem = blockIdx.x;
    while (rem > i) { rem -= i + 1; i++; }
    const int j = rem;
    const int b = b0 + blockIdx.y, kz = blockIdx.z;
    const float* xb = x + ((size_t)b * N_ + (size_t)kz * GRAM_KLEN) * C_;

    __shared__ float As[2][16][128];
    __shared__ float Bs[2][16][128];

    const int tid = threadIdx.x;
    const int tm = tid & 15, tn = tid >> 4;

    u64 acc[8][4];
#pragma unroll
    for (int q = 0; q < 8; q++)
#pragma unroll
        for (int p = 0; p < 4; p++) acc[q][p] = pack2(0.f, 0.f);

    float4 ra[2], rb[2];

    auto ldg = [&](int kt) {
#pragma unroll
        for (int l = 0; l < 2; l++) {
            int fid = tid + l * 256;
            int r = fid >> 5, cc = fid & 31;
            const float* src = xb + (size_t)(kt * 16 + r) * C_ + cc * 4;
            ra[l] = *(const float4*)(src + i * 128);
            rb[l] = *(const float4*)(src + j * 128);
        }
    };
    auto sts = [&](int s) {
#pragma unroll
        for (int l = 0; l < 2; l++) {
            int fid = tid + l * 256;
            int r = fid >> 5, cc = fid & 31;
            *(float4*)&As[s][r][cc * 4] = ra[l];
            *(float4*)&Bs[s][r][cc * 4] = rb[l];
        }
    };

    ldg(0); sts(0);
    __syncthreads();

    const int KT = GRAM_KLEN / 16;
    for (int kt = 0; kt < KT; ++kt) {
        const int s = kt & 1;
        if (kt + 1 < KT) ldg(kt + 1);
#pragma unroll
        for (int k = 0; k < 16; k++) {
            float4 a0 = *(const float4*)&As[s][k][tm * 8];
            float4 a1 = *(const float4*)&As[s][k][tm * 8 + 4];
            u64 b0r = *(const u64*)&Bs[s][k][tn * 8 + 0];
            u64 b1 = *(const u64*)&Bs[s][k][tn * 8 + 2];
            u64 b2 = *(const u64*)&Bs[s][k][tn * 8 + 4];
            u64 b3 = *(const u64*)&Bs[s][k][tn * 8 + 6];
            float av[8] = {a0.x, a0.y, a0.z, a0.w, a1.x, a1.y, a1.z, a1.w};
#pragma unroll
            for (int q = 0; q < 8; q++) {
                u64 ad = pack2(av[q], av[q]);
                acc[q][0] = ffma2(ad, b0r, acc[q][0]);
                acc[q][1] = ffma2(ad, b1, acc[q][1]);
                acc[q][2] = ffma2(ad, b2, acc[q][2]);
                acc[q][3] = ffma2(ad, b3, acc[q][3]);
            }
        }
        __syncthreads();
        if (kt + 1 < KT) {
            sts(s ^ 1);
            __syncthreads();
        }
    }

    float* Gb = g_G + (size_t)b * C_ * C_;
#pragma unroll
    for (int q = 0; q < 8; q++) {
        int gi = i * 128 + tm * 8 + q;
#pragma unroll
        for (int p = 0; p < 4; p++) {
            float lo, hi; unpack2(acc[q][p], lo, hi);
            int gj = j * 128 + tn * 8 + 2 * p;
            atomicAdd(&Gb[(size_t)gi * C_ + gj], lo);
            atomicAdd(&Gb[(size_t)gi * C_ + gj + 1], hi);
            if (i != j) {
                atomicAdd(&Gb[(size_t)gj * C_ + gi], lo);
                atomicAdd(&Gb[(size_t)(gj + 1) * C_ + gi], hi);
            }
        }
    }
}

// ---------------- diag norms --------------------------------------------------
__global__ void diagnorm_kernel(const float* __restrict__ Wqkv, int b0)
{
    const int b = b0 + blockIdx.y;
    const int lane = threadIdx.x & 31;
    const int w = threadIdx.x >> 5;
    const int c = blockIdx.x * 32 + lane;
    const float* T = g_T + (size_t)b * C_ * (2 * C_);

    float s0 = 0.f, s1 = 0.f, s2 = 0.f, s3 = 0.f;
    for (int r0 = w * 4; r0 < C_; r0 += 32) {
        s0 += Wqkv[(size_t)(r0 + 0) * QKV_COLS + c] * T[(size_t)(r0 + 0) * (2 * C_) + c];
        s1 += Wqkv[(size_t)(r0 + 1) * QKV_COLS + c] * T[(size_t)(r0 + 1) * (2 * C_) + c];
        s2 += Wqkv[(size_t)(r0 + 2) * QKV_COLS + c] * T[(size_t)(r0 + 2) * (2 * C_) + c];
        s3 += Wqkv[(size_t)(r0 + 3) * QKV_COLS + c] * T[(size_t)(r0 + 3) * (2 * C_) + c];
    }
    __shared__ float red[8][32];
    red[w][lane] = (s0 + s1) + (s2 + s3);
    __syncthreads();
    if (w == 0) {
        float t = 0.f;
#pragma unroll
        for (int r = 0; r < 8; r++) t += red[r][lane];
        g_rn[b * (2 * C_) + c] = 1.f / fmaxf(sqrtf(t), 1e-12f);
    }
}

// ---------------- S partials: g_S6[kc][bh] = Wq_h^T Tk_bh over K chunk -------
__global__ void __launch_bounds__(256)
s_kernel(const float* __restrict__ Wqkv, int bh0)
{
    const int bh = bh0 + blockIdx.x, b = bh >> 3, h = bh & 7;
    const int kc = blockIdx.y;
    const int tid = threadIdx.x;
    const int te = tid & 15, td = tid >> 4;

    __shared__ float qs[32][96];
    __shared__ float ks[32][96];

    u64 acc2[6][3];
#pragma unroll
    for (int q = 0; q < 6; q++)
#pragma unroll
        for (int p = 0; p < 3; p++) acc2[q][p] = pack2(0.f, 0.f);

    const float* Wq = Wqkv + h * HD;
    const float* Tk = g_T + (size_t)b * C_ * (2 * C_) + C_ + h * HD;

    for (int t = kc * 4; t < kc * 4 + 4; t++) {
#pragma unroll
        for (int l = 0; l < 3; l++) {
            int fid = tid + l * 256;
            int r = fid / 24, cc = fid % 24;
            *(float4*)&qs[r][cc * 4] =
                *(const float4*)(Wq + (size_t)(t * 32 + r) * QKV_COLS + cc * 4);
            *(float4*)&ks[r][cc * 4] =
                *(const float4*)(Tk + (size_t)(t * 32 + r) * (2 * C_) + cc * 4);
        }
        __syncthreads();
#pragma unroll 4
        for (int r = 0; r < 32; r++) {
            const u64* bp = (const u64*)&ks[r][te * 6];
            u64 b0 = bp[0], b1 = bp[1], b2 = bp[2];
#pragma unroll
            for (int q = 0; q < 6; q++) {
                float a = qs[r][td * 6 + q];
                u64 ad = pack2(a, a);
                acc2[q][0] = ffma2(ad, b0, acc2[q][0]);
                acc2[q][1] = ffma2(ad, b1, acc2[q][1]);
                acc2[q][2] = ffma2(ad, b2, acc2[q][2]);
            }
        }
        __syncthreads();
    }
    float* Sp = g_S6 + ((size_t)kc * (B_ * H_) + bh) * HD * HD;
#pragma unroll
    for (int q = 0; q < 6; q++)
#pragma unroll
        for (int p = 0; p < 3; p++) {
            float lo, hi; unpack2(acc2[q][p], lo, hi);
            *(float2*)&Sp[(td * 6 + q) * HD + te * 6 + 2 * p] = make_float2(lo, hi);
        }
}

// ---------------- sum partials + scale + softmax -> g_S ----------------------
__global__ void softmax_kernel(const float* __restrict__ temp, int bh0)
{
    const int bh = bh0 + blockIdx.x, b = bh >> 3, h = bh & 7;
    const int d = threadIdx.x;
    if (d >= HD) return;
    const float rq = g_rn[b * (2 * C_) + h * HD + d] * temp[h];
    const float* rk = g_rn + b * (2 * C_) + C_ + h * HD;
    const size_t rowoff = (size_t)bh * HD * HD + (size_t)d * HD;

    float vals[HD];
    float m = -1e30f;
    for (int e = 0; e < HD; e++) {
        float v = 0.f;
#pragma unroll
        for (int k = 0; k < SKC; k++)
            v += g_S6[(size_t)k * (B_ * H_ * HD * HD) + rowoff + e];
        v *= rq * rk[e];
        vals[e] = v;
        if (v > m) m = v;
    }
    float ssum = 0.f;
    for (int e = 0; e < HD; e++) {
        float v = expf(vals[e] - m);
        vals[e] = v;
        ssum += v;
    }
    float inv = 1.f / ssum;
    float* row = g_S + rowoff;
    for (int e = 0; e < HD; e++) row[e] = vals[e] * inv;
}

// ---------------- P_b[h*96+e, j] = sum_d attn_bh[d,e] * Wproj[h*96+d, j] -----
__global__ void __launch_bounds__(256)
p_kernel(const float* __restrict__ Wproj, int bh0)
{
    const int bh = bh0 + blockIdx.x, b = bh >> 3, h = bh & 7;
    const int jt = blockIdx.y;
    const int tid = threadIdx.x;
    const int er = tid >> 5, lane = tid & 31;

    __shared__ float ats[32][96];
    __shared__ float ws[32][128];

    u64 acc2[12][2];
#pragma unroll
    for (int q = 0; q < 12; q++) { acc2[q][0] = pack2(0.f, 0.f); acc2[q][1] = pack2(0.f, 0.f); }

    const float* Sp = g_S + (size_t)bh * HD * HD;
    const float* Wp = Wproj + (size_t)(h * HD) * C_ + jt * 128;

    for (int dc = 0; dc < 3; dc++) {
        __syncthreads();
#pragma unroll
        for (int l = 0; l < 3; l++) {
            int fid = tid + l * 256;
            int r = fid / 24, cc = fid % 24;
            *(float4*)&ats[r][cc * 4] = *(const float4*)(Sp + (size_t)(dc * 32 + r) * HD + cc * 4);
        }
#pragma unroll
        for (int l = 0; l < 4; l++) {
            int fid = tid + l * 256;
            int r = fid >> 5, cc = fid & 31;
            *(float4*)&ws[r][cc * 4] = *(const float4*)(Wp + (size_t)(dc * 32 + r) * C_ + cc * 4);
        }
        __syncthreads();
#pragma unroll 4
        for (int d = 0; d < 32; d++) {
            u64 w01 = *(const u64*)&ws[d][lane * 4];
            u64 w23 = *(const u64*)&ws[d][lane * 4 + 2];
#pragma unroll
            for (int q = 0; q < 12; q++) {
                float a = ats[d][er * 12 + q];
                u64 ad = pack2(a, a);
                acc2[q][0] = ffma2(ad, w01, acc2[q][0]);
                acc2[q][1] = ffma2(ad, w23, acc2[q][1]);
            }
        }
    }

    float* Pb = g_P + (size_t)b * C_ * C_;
#pragma unroll
    for (int q = 0; q < 12; q++) {
        float f0, f1, f2, f3;
        unpack2(acc2[q][0], f0, f1);
        unpack2(acc2[q][1], f2, f3);
        *(float4*)&Pb[(size_t)(h * HD + er * 12 + q) * C_ + jt * 128 + lane * 4] =
            make_float4(f0, f1, f2, f3);
    }
}

// ---------------- per-group chain --------------------------------------------
static void launch_group(int g, cudaStream_t st,
                         const float* x, const float* Wqkv, const float* temp,
                         const float* Wproj, const float* bproj, float* out,
                         float* dG, float* dT, float* dP, float* dQ)
{
    const int b0 = g * GB;
    const long long CC = (long long)C_ * C_;

    zeroG_kernel<<<NG4G / 256, 256, 0, st>>>(b0);
    gram_kernel<<<dim3(21, GB, GRAM_KSPLIT), 256, 0, st>>>(x, b0);

    // T_b = G_b @ [Wq|Wk]
    sgemm_kernel<<<dim3((2 * C_) / 128, C_ / 128, GB), 256, 0, st>>>(
        dG + (size_t)b0 * CC, Wqkv, dT + (size_t)b0 * C_ * 2 * C_, nullptr,
        C_, C_, QKV_COLS, 2 * C_, CC, (long long)C_ * 2 * C_, 0, 0);

    s_kernel<<<dim3(GB * H_, SKC), 256, 0, st>>>(Wqkv, b0 * H_);
    diagnorm_kernel<<<dim3((2 * C_) / 32, GB), 256, 0, st>>>(Wqkv, b0);
    softmax_kernel<<<GB * H_, 96, 0, st>>>(temp, b0 * H_);
    p_kernel<<<dim3(GB * H_, C_ / 128), 256, 0, st>>>(Wproj, b0 * H_);

    // Q_b = Wv @ P_b
    sgemm_kernel<<<dim3(C_ / 128, C_ / 128, GB), 256, 0, st>>>(
        Wqkv + 2 * C_, dP + (size_t)b0 * CC, dQ + (size_t)b0 * CC, nullptr,
        C_, QKV_COLS, C_, C_, 0, CC, CC, 0);

    // out rows [b0*N, (b0+GB)*N) = x @ Q_b + bproj
    sgemm_kernel<<<dim3(C_ / 128, (GB * N_) / 128, 1), 256, 0, st>>>(
        x + (size_t)b0 * N_ * C_, dQ + (size_t)b0 * CC,
        out + (size_t)b0 * N_ * C_, bproj,
        C_, C_, C_, C_, 0, 0, 0, CC);
}

// ---------------- launch ----------------------------------------------------
extern "C" void kernel_launch(void* const* d_in, const int* in_sizes, int n_in,
                              void* d_out, int out_size)
{
    const float* x     = (const float*)d_in[0];
    const float* Wqkv  = (const float*)d_in[1];
    const float* temp  = (const float*)d_in[2];
    const float* Wproj = (const float*)d_in[3];
    const float* bproj = (const float*)d_in[4];
    float* out = (float*)d_out;

    static float *dG = nullptr, *dT = nullptr, *dP = nullptr, *dQ = nullptr;
    static cudaStream_t ss[NGRP - 1] = {};
    static cudaEvent_t ev0 = nullptr, evB[NGRP - 1] = {};
    if (!dG) {
        cudaGetSymbolAddress((void**)&dG, g_G);
        cudaGetSymbolAddress((void**)&dT, g_T);
        cudaGetSymbolAddress((void**)&dP, g_P);
        cudaGetSymbolAddress((void**)&dQ, g_Q);
        cudaEventCreateWithFlags(&ev0, cudaEventDisableTiming);
        for (int i = 0; i < NGRP - 1; i++) {
            cudaStreamCreateWithFlags(&ss[i], cudaStreamNonBlocking);
            cudaEventCreateWithFlags(&evB[i], cudaEventDisableTiming);
        }
    }

    // fork: groups 1..3 onto side streams
    cudaEventRecord(ev0, 0);
    for (int i = 0; i < NGRP - 1; i++)
        cudaStreamWaitEvent(ss[i], ev0, 0);

    for (int i = 0; i < NGRP - 1; i++)
        launch_group(i + 1, ss[i], x, Wqkv, temp, Wproj, bproj, out, dG, dT, dP, dQ);
    launch_group(0, 0, x, Wqkv, temp, Wproj, bproj, out, dG, dT, dP, dQ);

    // join
    for (int i = 0; i < NGRP - 1; i++) {
        cudaEventRecord(evB[i], ss[i]);
        cudaStreamWaitEvent(0, evB[i], 0);
    }
}